// round 2
// baseline (speedup 1.0000x reference)
#include <cuda_runtime.h>

#define KNN   20
#define BB    8
#define NN    4096
#define PT    (BB * NN)          /* 32768  points */
#define ET    (PT * KNN)         /* 655360 edges  */
#define EPSBN 1e-5f

// ---------------------------------------------------------------------------
// Static device scratch (no allocations anywhere)
// ---------------------------------------------------------------------------
static __device__ float g_feat3[PT * 3];
static __device__ float g_xx[PT];
static __device__ float g_dist[(size_t)PT * NN];        // 512 MB
static __device__ int   g_idx[ET];
static __device__ float g_hA[(size_t)ET * 64];          // 160 MB
static __device__ float g_hB[(size_t)ET * 64];          // 160 MB
static __device__ float g_x1[PT * 64];
static __device__ float g_x2[PT * 64];
static __device__ float g_x3[PT * 64];
static __device__ float g_h6[(size_t)PT * 1024];        // 128 MB
static __device__ float g_h7[(size_t)PT * 512];
static __device__ float g_h8[(size_t)PT * 256];
static __device__ float g_gpart[BB * 16 * 1024];
static __device__ float g_gmax[BB * 1024];
static __device__ float g_sum[8 * 1024];
static __device__ float g_sumsq[8 * 1024];
static __device__ float g_scale[8 * 1024];
static __device__ float g_bias[8 * 1024];

__device__ __forceinline__ float lrelu(float v) { return v > 0.f ? v : 0.2f * v; }

__device__ __forceinline__ const float* statbuf(int s) {
    switch (s) {
        case 0:  return g_hA;
        case 1:  return g_hB;
        case 2:  return g_h6;
        case 3:  return g_h7;
        default: return g_h8;
    }
}

// ---------------------------------------------------------------------------
// Zero the BN statistic accumulators (must run each launch for graph replay)
// ---------------------------------------------------------------------------
__global__ void k_zero() {
    int t = blockIdx.x * 256 + threadIdx.x;
    if (t < 8 * 1024) { g_sum[t] = 0.f; g_sumsq[t] = 0.f; }
}

// ---------------------------------------------------------------------------
// Transpose x [B,3,N] -> feat3 [P,3] and squared norms
// ---------------------------------------------------------------------------
__global__ void k_prep3(const float* __restrict__ x) {
    int p = blockIdx.x * 256 + threadIdx.x;
    if (p >= PT) return;
    int b = p >> 12, n = p & (NN - 1);
    const float* xb = x + (size_t)b * 3 * NN;
    float a0 = xb[n], a1 = xb[NN + n], a2 = xb[2 * NN + n];
    g_feat3[p * 3 + 0] = a0;
    g_feat3[p * 3 + 1] = a1;
    g_feat3[p * 3 + 2] = a2;
    g_xx[p] = a0 * a0 + a1 * a1 + a2 * a2;
}

// squared norms of [P,64] feature arrays (sel: 1 -> x1, 2 -> x2); warp per row
__global__ void k_xx64(int sel) {
    const float* f = (sel == 1) ? g_x1 : g_x2;
    int gt = blockIdx.x * 256 + threadIdx.x;
    int w = gt >> 5, lane = gt & 31;
    if (w >= PT) return;
    const float* r = f + ((size_t)w << 6);
    float v0 = r[lane], v1 = r[lane + 32];
    float s = v0 * v0 + v1 * v1;
#pragma unroll
    for (int o = 16; o; o >>= 1) s += __shfl_down_sync(0xffffffffu, s, o);
    if (lane == 0) g_xx[w] = s;
}

// ---------------------------------------------------------------------------
// Pairwise neg. squared distance: dist[b,i,j] = 2<xi,xj> - |xi|^2 - |xj|^2
// grid (N/64, N/64, B), 256 threads, 64x64 tile, 4x4 per thread
// ---------------------------------------------------------------------------
template <int C>
__global__ __launch_bounds__(256) void k_dist(int sel) {
    __shared__ __align__(16) float As[C][68];
    __shared__ __align__(16) float Bs[C][68];
    __shared__ float sxi[64], sxj[64];
    const float* f = (C == 3) ? g_feat3 : ((sel == 1) ? g_x1 : g_x2);
    int b  = blockIdx.z;
    int j0 = blockIdx.x << 6, i0 = blockIdx.y << 6;
    int tid = threadIdx.x, tx = tid & 15, ty = tid >> 4;
    int bi = b * NN + i0, bj = b * NN + j0;
    for (int l = tid; l < 64 * C; l += 256) {
        int r = l / C, c = l - r * C;
        As[c][r] = f[(size_t)(bi + r) * C + c];
        Bs[c][r] = f[(size_t)(bj + r) * C + c];
    }
    if (tid < 64) sxi[tid] = g_xx[bi + tid];
    else if (tid < 128) sxj[tid - 64] = g_xx[bj + tid - 64];
    __syncthreads();
    float acc[4][4] = {};
    int r4 = ty << 2, c4 = tx << 2;
#pragma unroll
    for (int k = 0; k < C; k++) {
        float4 a4 = *(const float4*)&As[k][r4];
        float4 b4 = *(const float4*)&Bs[k][c4];
        float av[4] = {a4.x, a4.y, a4.z, a4.w};
        float bv[4] = {b4.x, b4.y, b4.z, b4.w};
#pragma unroll
        for (int ii = 0; ii < 4; ii++)
#pragma unroll
            for (int jj = 0; jj < 4; jj++)
                acc[ii][jj] = fmaf(av[ii], bv[jj], acc[ii][jj]);
    }
#pragma unroll
    for (int ii = 0; ii < 4; ii++) {
        int i = i0 + r4 + ii;
        float xi = sxi[r4 + ii];
#pragma unroll
        for (int jj = 0; jj < 4; jj++)
            g_dist[(size_t)(b * NN + i) * NN + j0 + c4 + jj] =
                2.f * acc[ii][jj] - xi - sxj[c4 + jj];
    }
}

// ---------------------------------------------------------------------------
// Top-K (largest) per row of g_dist. 128 threads per row.
// Per-thread sorted top-20 insertion list (registers) -> head merge in smem.
// ---------------------------------------------------------------------------
__global__ __launch_bounds__(128) void k_topk() {
    __shared__ float sv[128 * KNN];
    __shared__ int   si[128 * KNN];
    __shared__ int   spos[128];
    __shared__ float wv[4];
    __shared__ int   wi[4], wt[4];
    int row = blockIdx.x;
    int tid = threadIdx.x;
    const float* d = g_dist + (size_t)row * NN;

    float lv[KNN];
    int   li[KNN];
#pragma unroll
    for (int q = 0; q < KNN; q++) { lv[q] = -3.0e38f; li[q] = 0x7fffffff; }

    for (int j = tid; j < NN; j += 128) {
        float v = d[j];
        if (v > lv[KNN - 1]) {
#pragma unroll
            for (int q = KNN - 1; q > 0; q--) {
                float pv = lv[q - 1]; int pi = li[q - 1];
                if (v > pv)           { lv[q] = pv; li[q] = pi; }
                else if (v > lv[q])   { lv[q] = v;  li[q] = j;  }
            }
            if (v > lv[0]) { lv[0] = v; li[0] = j; }
        }
    }
#pragma unroll
    for (int q = 0; q < KNN; q++) { sv[tid * KNN + q] = lv[q]; si[tid * KNN + q] = li[q]; }
    spos[tid] = 0;
    __syncthreads();

    for (int r = 0; r < KNN; r++) {
        int pos = spos[tid];
        float hv = (pos < KNN) ? sv[tid * KNN + pos] : -3.0e38f;
        int   hx = (pos < KNN) ? si[tid * KNN + pos] : 0x7fffffff;
        float bv = hv; int bx = hx; int bt = tid;
#pragma unroll
        for (int off = 16; off; off >>= 1) {
            float ov = __shfl_down_sync(0xffffffffu, bv, off);
            int   ox = __shfl_down_sync(0xffffffffu, bx, off);
            int   ot = __shfl_down_sync(0xffffffffu, bt, off);
            if (ov > bv || (ov == bv && ox < bx)) { bv = ov; bx = ox; bt = ot; }
        }
        if ((tid & 31) == 0) { wv[tid >> 5] = bv; wi[tid >> 5] = bx; wt[tid >> 5] = bt; }
        __syncthreads();
        if (tid == 0) {
            float Bv = wv[0]; int Bx = wi[0], Bt = wt[0];
#pragma unroll
            for (int t2 = 1; t2 < 4; t2++)
                if (wv[t2] > Bv || (wv[t2] == Bv && wi[t2] < Bx)) { Bv = wv[t2]; Bx = wi[t2]; Bt = wt[t2]; }
            g_idx[(size_t)row * KNN + r] = Bx;
            spos[Bt]++;
        }
        __syncthreads();
    }
}

// ---------------------------------------------------------------------------
// Edge layer 1: gather [xj-xi, xi] (6 dims) @ W1^T -> raw hA [E,64]
// ---------------------------------------------------------------------------
__global__ __launch_bounds__(256) void k_edge1(const float* __restrict__ W1) {
    __shared__ __align__(16) float Af[6][68];
    __shared__ __align__(16) float Bw[6][68];
    int e0 = blockIdx.x << 6, tid = threadIdx.x;
    if (tid < 64) {
        int e = e0 + tid;
        int p = e / KNN;
        int q = (p >> 12) * NN + g_idx[e];
        float p0 = g_feat3[p * 3], p1 = g_feat3[p * 3 + 1], p2 = g_feat3[p * 3 + 2];
        float q0 = g_feat3[q * 3], q1 = g_feat3[q * 3 + 1], q2 = g_feat3[q * 3 + 2];
        Af[0][tid] = q0 - p0; Af[1][tid] = q1 - p1; Af[2][tid] = q2 - p2;
        Af[3][tid] = p0;      Af[4][tid] = p1;      Af[5][tid] = p2;
    } else if (tid < 128) {
        int o = tid - 64;
#pragma unroll
        for (int c = 0; c < 6; c++) Bw[c][o] = W1[o * 6 + c];
    }
    __syncthreads();
    int tx = tid & 15, ty = tid >> 4;
    int r4 = ty << 2, c4 = tx << 2;
    float acc[4][4] = {};
#pragma unroll
    for (int k = 0; k < 6; k++) {
        float4 a4 = *(const float4*)&Af[k][r4];
        float4 b4 = *(const float4*)&Bw[k][c4];
        float av[4] = {a4.x, a4.y, a4.z, a4.w};
        float bv[4] = {b4.x, b4.y, b4.z, b4.w};
#pragma unroll
        for (int ii = 0; ii < 4; ii++)
#pragma unroll
            for (int jj = 0; jj < 4; jj++)
                acc[ii][jj] = fmaf(av[ii], bv[jj], acc[ii][jj]);
    }
#pragma unroll
    for (int ii = 0; ii < 4; ii++)
#pragma unroll
        for (int jj = 0; jj < 4; jj++)
            g_hA[(size_t)(e0 + r4 + ii) * 64 + c4 + jj] = acc[ii][jj];
}

// ---------------------------------------------------------------------------
// Edge layers 2/4: act_slot(hA) [E,64] @ W^T [64,64] -> raw hB
// ---------------------------------------------------------------------------
__global__ __launch_bounds__(256) void k_edge64(const float* __restrict__ W, int slot) {
    __shared__ __align__(16) float As[64][68];
    __shared__ __align__(16) float Bs[64][68];
    __shared__ float sS[64], sB[64];
    int e0 = blockIdx.x << 6, tid = threadIdx.x;
    if (tid < 64) { sS[tid] = g_scale[slot * 1024 + tid]; sB[tid] = g_bias[slot * 1024 + tid]; }
    __syncthreads();
    for (int l = tid; l < 4096; l += 256) {
        int r = l >> 6, c = l & 63;
        float t = g_hA[(size_t)(e0 + r) * 64 + c] * sS[c] + sB[c];
        As[c][r] = lrelu(t);
        Bs[l & 63][l >> 6] = W[(size_t)(l >> 6) * 64 + (l & 63)];
    }
    __syncthreads();
    int tx = tid & 15, ty = tid >> 4;
    int r4 = ty << 2, c4 = tx << 2;
    float acc[4][4] = {};
#pragma unroll
    for (int k = 0; k < 64; k++) {
        float4 a4 = *(const float4*)&As[k][r4];
        float4 b4 = *(const float4*)&Bs[k][c4];
        float av[4] = {a4.x, a4.y, a4.z, a4.w};
        float bv[4] = {b4.x, b4.y, b4.z, b4.w};
#pragma unroll
        for (int ii = 0; ii < 4; ii++)
#pragma unroll
            for (int jj = 0; jj < 4; jj++)
                acc[ii][jj] = fmaf(av[ii], bv[jj], acc[ii][jj]);
    }
#pragma unroll
    for (int ii = 0; ii < 4; ii++)
#pragma unroll
        for (int jj = 0; jj < 4; jj++)
            g_hB[(size_t)(e0 + r4 + ii) * 64 + c4 + jj] = acc[ii][jj];
}

// ---------------------------------------------------------------------------
// Edge layers 3/5: gathered 128-dim edge feature [xj-xi, xi] @ W^T [64,128]
// src = x1 or x2 (already activated). Output raw -> g_hA.
// ---------------------------------------------------------------------------
__global__ __launch_bounds__(256) void k_edgeGather(const float* __restrict__ W, int srcSel) {
    __shared__ __align__(16) float As[64][68];
    __shared__ __align__(16) float Bs[64][68];
    __shared__ int sP[64], sQ[64];
    const float* src = (srcSel == 1) ? g_x1 : g_x2;
    int e0 = blockIdx.x << 6, tid = threadIdx.x;
    if (tid < 64) {
        int e = e0 + tid;
        int p = e / KNN;
        sP[tid] = p;
        sQ[tid] = (p >> 12) * NN + g_idx[e];
    }
    __syncthreads();
    int tx = tid & 15, ty = tid >> 4;
    int r4 = ty << 2, c4 = tx << 2;
    float acc[4][4] = {};
    for (int half = 0; half < 2; half++) {
        for (int l = tid; l < 4096; l += 256) {
            int c = l & 63, r = l >> 6;
            float v;
            if (half == 0)
                v = src[(size_t)sQ[r] * 64 + c] - src[(size_t)sP[r] * 64 + c];
            else
                v = src[(size_t)sP[r] * 64 + c];
            As[c][r] = v;
            Bs[l & 63][l >> 6] = W[(size_t)(l >> 6) * 128 + half * 64 + (l & 63)];
        }
        __syncthreads();
#pragma unroll
        for (int k = 0; k < 64; k++) {
            float4 a4 = *(const float4*)&As[k][r4];
            float4 b4 = *(const float4*)&Bs[k][c4];
            float av[4] = {a4.x, a4.y, a4.z, a4.w};
            float bv[4] = {b4.x, b4.y, b4.z, b4.w};
#pragma unroll
            for (int ii = 0; ii < 4; ii++)
#pragma unroll
                for (int jj = 0; jj < 4; jj++)
                    acc[ii][jj] = fmaf(av[ii], bv[jj], acc[ii][jj]);
        }
        __syncthreads();
    }
#pragma unroll
    for (int ii = 0; ii < 4; ii++)
#pragma unroll
        for (int jj = 0; jj < 4; jj++)
            g_hA[(size_t)(e0 + r4 + ii) * 64 + c4 + jj] = acc[ii][jj];
}

// ---------------------------------------------------------------------------
// Point GEMMs (layers 6/7/8). Modes:
//   0: Cin=192  A = [x1,x2,x3]               out g_h6
//   1: Cin=1216 A = [gmax(b),x1,x2,x3]       out g_h7
//   2: Cin=512  A = act_slot(g_h7)           out g_h8
// ---------------------------------------------------------------------------
__global__ __launch_bounds__(256) void k_point(const float* __restrict__ W,
                                               int Cin, int Cout, int mode,
                                               int slot, int outSel) {
    __shared__ __align__(16) float As[64][68];
    __shared__ __align__(16) float Bs[64][68];
    int c0 = blockIdx.x << 6, r0 = blockIdx.y << 6;
    int tid = threadIdx.x, tx = tid & 15, ty = tid >> 4;
    int r4 = ty << 2, c4 = tx << 2;
    int b = r0 >> 12;
    float acc[4][4] = {};
    for (int k0 = 0; k0 < Cin; k0 += 64) {
        for (int l = tid; l < 4096; l += 256) {
            int kk = l & 63, r = l >> 6;
            int c = k0 + kk, row = r0 + r;
            float v;
            if (mode == 0) {
                v = (c < 64) ? g_x1[(size_t)row * 64 + c]
                  : (c < 128) ? g_x2[(size_t)row * 64 + c - 64]
                              : g_x3[(size_t)row * 64 + c - 128];
            } else if (mode == 1) {
                if (c < 1024) v = g_gmax[b * 1024 + c];
                else {
                    int cc = c - 1024;
                    v = (cc < 64) ? g_x1[(size_t)row * 64 + cc]
                      : (cc < 128) ? g_x2[(size_t)row * 64 + cc - 64]
                                   : g_x3[(size_t)row * 64 + cc - 128];
                }
            } else {
                float raw = g_h7[(size_t)row * 512 + c];
                float t = raw * g_scale[slot * 1024 + c] + g_bias[slot * 1024 + c];
                v = lrelu(t);
            }
            As[kk][r] = v;
            Bs[l & 63][l >> 6] = W[(size_t)(c0 + (l >> 6)) * Cin + k0 + (l & 63)];
        }
        __syncthreads();
#pragma unroll
        for (int k = 0; k < 64; k++) {
            float4 a4 = *(const float4*)&As[k][r4];
            float4 b4 = *(const float4*)&Bs[k][c4];
            float av[4] = {a4.x, a4.y, a4.z, a4.w};
            float bv[4] = {b4.x, b4.y, b4.z, b4.w};
#pragma unroll
            for (int ii = 0; ii < 4; ii++)
#pragma unroll
                for (int jj = 0; jj < 4; jj++)
                    acc[ii][jj] = fmaf(av[ii], bv[jj], acc[ii][jj]);
        }
        __syncthreads();
    }
    float* out = (outSel == 0) ? g_h6 : (outSel == 1 ? g_h7 : g_h8);
#pragma unroll
    for (int ii = 0; ii < 4; ii++)
#pragma unroll
        for (int jj = 0; jj < 4; jj++)
            out[(size_t)(r0 + r4 + ii) * Cout + c0 + c4 + jj] = acc[ii][jj];
}

// ---------------------------------------------------------------------------
// BN statistics: per-channel sum / sumsq of a raw [M,C] tensor (C power of 2)
// Fixed-channel register accumulation; grid MUST be 512 blocks (stride 131072)
// ---------------------------------------------------------------------------
__global__ __launch_bounds__(256) void k_stats(int inSel, long long M, int C, int slot) {
    __shared__ float ss[1024], sq[1024];
    const float* h = statbuf(inSel);
    int tid = threadIdx.x;
    for (int i = tid; i < C; i += 256) { ss[i] = 0.f; sq[i] = 0.f; }
    __syncthreads();
    long long total  = M * (long long)C;
    long long stride = (long long)gridDim.x * 256;
    long long i0     = (long long)blockIdx.x * 256 + tid;
    int c0 = (int)(i0 & (long long)(C - 1));
    float s = 0.f, q = 0.f;
    for (long long i = i0; i < total; i += stride) {
        float v = h[i];
        s += v; q += v * v;
    }
    atomicAdd(&ss[c0], s);
    atomicAdd(&sq[c0], q);
    __syncthreads();
    for (int i = tid; i < C; i += 256) {
        atomicAdd(&g_sum[slot * 1024 + i], ss[i]);
        atomicAdd(&g_sumsq[slot * 1024 + i], sq[i]);
    }
}

// fold (gamma, beta, mean, var) -> per-channel scale/bias
__global__ void k_fin(int slot, int C, float invM,
                      const float* __restrict__ g, const float* __restrict__ b) {
    int c = blockIdx.x * 256 + threadIdx.x;
    if (c >= C) return;
    float mean = g_sum[slot * 1024 + c] * invM;
    float var  = g_sumsq[slot * 1024 + c] * invM - mean * mean;
    float sc   = g[c] * rsqrtf(var + EPSBN);
    g_scale[slot * 1024 + c] = sc;
    g_bias[slot * 1024 + c]  = b[c] - mean * sc;
}

// ---------------------------------------------------------------------------
// Max over k edges of act_slot(h) -> x{1,2,3}[P,64]
// ---------------------------------------------------------------------------
__global__ void k_maxe(int inSel, int slot, int outSel) {
    const float* h = (inSel == 0) ? g_hA : g_hB;
    float* out = (outSel == 1) ? g_x1 : (outSel == 2 ? g_x2 : g_x3);
    int t = blockIdx.x * 256 + threadIdx.x;
    if (t >= PT * 64) return;
    int p = t >> 6, c = t & 63;
    float sc = g_scale[slot * 1024 + c], bi = g_bias[slot * 1024 + c];
    const float* base = h + ((size_t)p * KNN) * 64 + c;
    float m = -3.0e38f;
#pragma unroll
    for (int j = 0; j < KNN; j++) {
        float v = lrelu(base[j * 64] * sc + bi);
        m = fmaxf(m, v);
    }
    out[t] = m;
}

// ---------------------------------------------------------------------------
// Global max pool over N of act_slot5(h6): partial (16 chunks) + combine
// ---------------------------------------------------------------------------
__global__ __launch_bounds__(256) void k_gmax1() {
    int b = blockIdx.y, chunk = blockIdx.x, tid = threadIdx.x;
    float m[4]  = {-3.0e38f, -3.0e38f, -3.0e38f, -3.0e38f};
    float s[4], bi[4];
#pragma unroll
    for (int u = 0; u < 4; u++) {
        int c = tid + 256 * u;
        s[u]  = g_scale[5 * 1024 + c];
        bi[u] = g_bias[5 * 1024 + c];
    }
    for (int r = 0; r < 256; r++) {
        const float* hr = g_h6 + (size_t)(b * NN + chunk * 256 + r) * 1024;
#pragma unroll
        for (int u = 0; u < 4; u++) {
            float t = lrelu(hr[tid + 256 * u] * s[u] + bi[u]);
            m[u] = fmaxf(m[u], t);
        }
    }
#pragma unroll
    for (int u = 0; u < 4; u++)
        g_gpart[(size_t)(b * 16 + chunk) * 1024 + tid + 256 * u] = m[u];
}

__global__ void k_gmax2() {
    int t = blockIdx.x * 256 + threadIdx.x;
    if (t >= BB * 1024) return;
    int b = t >> 10, c = t & 1023;
    float m = -3.0e38f;
#pragma unroll
    for (int ch = 0; ch < 16; ch++)
        m = fmaxf(m, g_gpart[(size_t)(b * 16 + ch) * 1024 + c]);
    g_gmax[t] = m;
}

// ---------------------------------------------------------------------------
// Final: out[P,9] = act_slot7(h8) @ W9^T   (no BN/act after W9)
// ---------------------------------------------------------------------------
__global__ void k_out9(const float* __restrict__ W9, float* __restrict__ out) {
    int t = blockIdx.x * 256 + threadIdx.x;
    if (t >= PT * 9) return;
    int p = t / 9, o = t - p * 9;
    const float* row = g_h8 + (size_t)p * 256;
    const float* w   = W9 + o * 256;
    float acc = 0.f;
#pragma unroll 4
    for (int k = 0; k < 256; k++) {
        float v = lrelu(row[k] * g_scale[7 * 1024 + k] + g_bias[7 * 1024 + k]);
        acc = fmaf(v, w[k], acc);
    }
    out[t] = acc;
}

// ---------------------------------------------------------------------------
// Host launcher
// ---------------------------------------------------------------------------
extern "C" void kernel_launch(void* const* d_in, const int* in_sizes, int n_in,
                              void* d_out, int out_size) {
    // Two possible input orderings:
    //  A) setup_inputs dict order: x, k, W1..W9, g1,b1..g8,b8  (in_sizes[1]==1)
    //  B) reference signature:     x, W1..W9, g1,b1..g8,b8, k
    int base = (in_sizes[1] == 1) ? 2 : 1;
    const float* x = (const float*)d_in[0];
    const float* W[9];
    const float* G[8];
    const float* Bt[8];
    for (int i = 0; i < 9; i++) W[i] = (const float*)d_in[base + i];
    for (int i = 0; i < 8; i++) {
        G[i]  = (const float*)d_in[base + 9 + 2 * i];
        Bt[i] = (const float*)d_in[base + 10 + 2 * i];
    }
    float* out = (float*)d_out;

    const float invE = 1.f / (float)ET;
    const float invP = 1.f / (float)PT;

    k_zero<<<32, 256>>>();
    k_prep3<<<PT / 256, 256>>>(x);

    // ---- stage 1: knn on xyz, edge layers 1-2, maxpool -> x1 ----
    k_dist<3><<<dim3(64, 64, BB), 256>>>(0);
    k_topk<<<PT, 128>>>();
    k_edge1<<<ET / 64, 256>>>(W[0]);
    k_stats<<<512, 256>>>(0, (long long)ET, 64, 0);
    k_fin<<<1, 256>>>(0, 64, invE, G[0], Bt[0]);
    k_edge64<<<ET / 64, 256>>>(W[1], 0);
    k_stats<<<512, 256>>>(1, (long long)ET, 64, 1);
    k_fin<<<1, 256>>>(1, 64, invE, G[1], Bt[1]);
    k_maxe<<<PT * 64 / 256, 256>>>(1, 1, 1);

    // ---- stage 2: knn on x1, edge layers 3-4, maxpool -> x2 ----
    k_xx64<<<PT * 32 / 256, 256>>>(1);
    k_dist<64><<<dim3(64, 64, BB), 256>>>(1);
    k_topk<<<PT, 128>>>();
    k_edgeGather<<<ET / 64, 256>>>(W[2], 1);
    k_stats<<<512, 256>>>(0, (long long)ET, 64, 2);
    k_fin<<<1, 256>>>(2, 64, invE, G[2], Bt[2]);
    k_edge64<<<ET / 64, 256>>>(W[3], 2);
    k_stats<<<512, 256>>>(1, (long long)ET, 64, 3);
    k_fin<<<1, 256>>>(3, 64, invE, G[3], Bt[3]);
    k_maxe<<<PT * 64 / 256, 256>>>(1, 3, 2);

    // ---- stage 3: knn on x2, edge layer 5, maxpool -> x3 ----
    k_xx64<<<PT * 32 / 256, 256>>>(2);
    k_dist<64><<<dim3(64, 64, BB), 256>>>(2);
    k_topk<<<PT, 128>>>();
    k_edgeGather<<<ET / 64, 256>>>(W[4], 2);
    k_stats<<<512, 256>>>(0, (long long)ET, 64, 4);
    k_fin<<<1, 256>>>(4, 64, invE, G[4], Bt[4]);
    k_maxe<<<PT * 64 / 256, 256>>>(0, 4, 3);

    // ---- point layers 6-9 ----
    k_point<<<dim3(16, PT / 64), 256>>>(W[5], 192, 1024, 0, 0, 0);
    k_stats<<<512, 256>>>(2, (long long)PT, 1024, 5);
    k_fin<<<4, 256>>>(5, 1024, invP, G[5], Bt[5]);
    k_gmax1<<<dim3(16, BB), 256>>>();
    k_gmax2<<<32, 256>>>();
    k_point<<<dim3(8, PT / 64), 256>>>(W[6], 1216, 512, 1, 0, 1);
    k_stats<<<512, 256>>>(3, (long long)PT, 512, 6);
    k_fin<<<2, 256>>>(6, 512, invP, G[6], Bt[6]);
    k_point<<<dim3(4, PT / 64), 256>>>(W[7], 512, 256, 2, 6, 2);
    k_stats<<<512, 256>>>(4, (long long)PT, 256, 7);
    k_fin<<<1, 256>>>(7, 256, invP, G[7], Bt[7]);
    k_out9<<<(PT * 9 + 255) / 256, 256>>>(W[8], out);
}

// round 4
// speedup vs baseline: 1.2032x; 1.2032x over previous
#include <cuda_runtime.h>

#define KNN   20
#define BB    8
#define NN    4096
#define PT    (BB * NN)          /* 32768  points */
#define ET    (PT * KNN)         /* 655360 edges  */
#define EPSBN 1e-5f

// ---------------------------------------------------------------------------
// Static device scratch (no allocations anywhere)
// ---------------------------------------------------------------------------
static __device__ float g_feat3[PT * 3];
static __device__ float g_xx[PT];
static __device__ float g_dist[(size_t)PT * NN];        // 512 MB
static __device__ int   g_idx[ET];
static __device__ float g_hA[(size_t)ET * 64];          // 160 MB
static __device__ float g_hB[(size_t)ET * 64];          // 160 MB
static __device__ float g_x1[PT * 64];
static __device__ float g_x2[PT * 64];
static __device__ float g_x3[PT * 64];
static __device__ float g_h6[(size_t)PT * 1024];        // 128 MB
static __device__ float g_h7[(size_t)PT * 512];
static __device__ float g_h8[(size_t)PT * 256];
static __device__ float g_gpart[BB * 16 * 1024];
static __device__ float g_gmax[BB * 1024];
static __device__ float g_sum[8 * 1024];
static __device__ float g_sumsq[8 * 1024];
static __device__ float g_scale[8 * 1024];
static __device__ float g_bias[8 * 1024];

__device__ __forceinline__ float lrelu(float v) { return v > 0.f ? v : 0.2f * v; }

__device__ __forceinline__ const float* statbuf(int s) {
    switch (s) {
        case 0:  return g_hA;
        case 1:  return g_hB;
        case 2:  return g_h6;
        case 3:  return g_h7;
        default: return g_h8;
    }
}

// ---------------------------------------------------------------------------
// Zero the BN statistic accumulators (must run each launch for graph replay)
// ---------------------------------------------------------------------------
__global__ void k_zero() {
    int t = blockIdx.x * 256 + threadIdx.x;
    if (t < 8 * 1024) { g_sum[t] = 0.f; g_sumsq[t] = 0.f; }
}

// ---------------------------------------------------------------------------
// Transpose x [B,3,N] -> feat3 [P,3] and squared norms
// ---------------------------------------------------------------------------
__global__ void k_prep3(const float* __restrict__ x) {
    int p = blockIdx.x * 256 + threadIdx.x;
    if (p >= PT) return;
    int b = p >> 12, n = p & (NN - 1);
    const float* xb = x + (size_t)b * 3 * NN;
    float a0 = xb[n], a1 = xb[NN + n], a2 = xb[2 * NN + n];
    g_feat3[p * 3 + 0] = a0;
    g_feat3[p * 3 + 1] = a1;
    g_feat3[p * 3 + 2] = a2;
    g_xx[p] = a0 * a0 + a1 * a1 + a2 * a2;
}

// squared norms of [P,64] feature arrays (sel: 1 -> x1, 2 -> x2); warp per row
__global__ void k_xx64(int sel) {
    const float* f = (sel == 1) ? g_x1 : g_x2;
    int gt = blockIdx.x * 256 + threadIdx.x;
    int w = gt >> 5, lane = gt & 31;
    if (w >= PT) return;
    const float* r = f + ((size_t)w << 6);
    float v0 = r[lane], v1 = r[lane + 32];
    float s = v0 * v0 + v1 * v1;
#pragma unroll
    for (int o = 16; o; o >>= 1) s += __shfl_down_sync(0xffffffffu, s, o);
    if (lane == 0) g_xx[w] = s;
}

// ---------------------------------------------------------------------------
// Pairwise neg. squared distance: dist[b,i,j] = 2<xi,xj> - |xi|^2 - |xj|^2
// grid (N/64, N/64, B), 256 threads, 64x64 tile, 4x4 per thread
// ---------------------------------------------------------------------------
template <int C>
__global__ __launch_bounds__(256) void k_dist(int sel) {
    __shared__ __align__(16) float As[C][68];
    __shared__ __align__(16) float Bs[C][68];
    __shared__ float sxi[64], sxj[64];
    const float* f = (C == 3) ? g_feat3 : ((sel == 1) ? g_x1 : g_x2);
    int b  = blockIdx.z;
    int j0 = blockIdx.x << 6, i0 = blockIdx.y << 6;
    int tid = threadIdx.x, tx = tid & 15, ty = tid >> 4;
    int bi = b * NN + i0, bj = b * NN + j0;
    for (int l = tid; l < 64 * C; l += 256) {
        int r = l / C, c = l - r * C;
        As[c][r] = f[(size_t)(bi + r) * C + c];
        Bs[c][r] = f[(size_t)(bj + r) * C + c];
    }
    if (tid < 64) sxi[tid] = g_xx[bi + tid];
    else if (tid < 128) sxj[tid - 64] = g_xx[bj + tid - 64];
    __syncthreads();
    float acc[4][4] = {};
    int r4 = ty << 2, c4 = tx << 2;
#pragma unroll
    for (int k = 0; k < C; k++) {
        float4 a4 = *(const float4*)&As[k][r4];
        float4 b4 = *(const float4*)&Bs[k][c4];
        float av[4] = {a4.x, a4.y, a4.z, a4.w};
        float bv[4] = {b4.x, b4.y, b4.z, b4.w};
#pragma unroll
        for (int ii = 0; ii < 4; ii++)
#pragma unroll
            for (int jj = 0; jj < 4; jj++)
                acc[ii][jj] = fmaf(av[ii], bv[jj], acc[ii][jj]);
    }
#pragma unroll
    for (int ii = 0; ii < 4; ii++) {
        int i = i0 + r4 + ii;
        float xi = sxi[r4 + ii];
#pragma unroll
        for (int jj = 0; jj < 4; jj++)
            g_dist[(size_t)(b * NN + i) * NN + j0 + c4 + jj] =
                2.f * acc[ii][jj] - xi - sxj[c4 + jj];
    }
}

// ---------------------------------------------------------------------------
// Top-K (largest) per row: tournament-with-replacement.
// 128 threads/row; thread t owns 32 contiguous elements in registers.
// 20 rounds: block argmax over per-thread maxima (u64 shuffle reduce),
// winner masks its extracted slot and rescans its 32 registers.
// ---------------------------------------------------------------------------
__global__ __launch_bounds__(128) void k_topk() {
    __shared__ unsigned long long swmax[4];
    __shared__ int sbwin;
    int row = blockIdx.x;
    int tid = threadIdx.x;
    const float4* d4 = (const float4*)(g_dist + (size_t)row * NN) + tid * 8;

    float v[32];
#pragma unroll
    for (int q = 0; q < 8; q++) {
        float4 t4 = d4[q];
        v[4 * q + 0] = t4.x; v[4 * q + 1] = t4.y;
        v[4 * q + 2] = t4.z; v[4 * q + 3] = t4.w;
    }
    unsigned mask = 0u;
    float curv = v[0];
    int   curp = 0;
#pragma unroll
    for (int i = 1; i < 32; i++)
        if (v[i] > curv) { curv = v[i]; curp = i; }

    for (int r = 0; r < KNN; r++) {
        // orderable key: monotone uint transform of float (handles +/-0, negatives)
        unsigned ub = __float_as_uint(curv);
        ub = (ub & 0x80000000u) ? ~ub : (ub | 0x80000000u);
        unsigned long long key = ((unsigned long long)ub << 32) | (unsigned)tid;
#pragma unroll
        for (int o = 16; o; o >>= 1) {
            unsigned long long ok = __shfl_down_sync(0xffffffffu, key, o);
            if (ok > key) key = ok;
        }
        if ((tid & 31) == 0) swmax[tid >> 5] = key;
        __syncthreads();
        if (tid == 0) {
            unsigned long long best = swmax[0];
#pragma unroll
            for (int w = 1; w < 4; w++)
                if (swmax[w] > best) best = swmax[w];
            sbwin = (int)(unsigned)best;
        }
        __syncthreads();
        if (tid == sbwin) {
            g_idx[(size_t)row * KNN + r] = tid * 32 + curp;
            mask |= 1u << curp;
            curv = -3.0e38f;
            curp = 0;
#pragma unroll
            for (int i = 0; i < 32; i++) {
                bool ok = !(mask & (1u << i)) && (v[i] > curv);
                if (ok) { curv = v[i]; curp = i; }
            }
        }
        // next round's __syncthreads (after leader writes) orders everything
    }
}

// ---------------------------------------------------------------------------
// Edge layer 1: gather [xj-xi, xi] (6 dims) @ W1^T -> raw hA [E,64]
// ---------------------------------------------------------------------------
__global__ __launch_bounds__(256) void k_edge1(const float* __restrict__ W1) {
    __shared__ __align__(16) float Af[6][68];
    __shared__ __align__(16) float Bw[6][68];
    int e0 = blockIdx.x << 6, tid = threadIdx.x;
    if (tid < 64) {
        int e = e0 + tid;
        int p = e / KNN;
        int q = (p >> 12) * NN + g_idx[e];
        float p0 = g_feat3[p * 3], p1 = g_feat3[p * 3 + 1], p2 = g_feat3[p * 3 + 2];
        float q0 = g_feat3[q * 3], q1 = g_feat3[q * 3 + 1], q2 = g_feat3[q * 3 + 2];
        Af[0][tid] = q0 - p0; Af[1][tid] = q1 - p1; Af[2][tid] = q2 - p2;
        Af[3][tid] = p0;      Af[4][tid] = p1;      Af[5][tid] = p2;
    } else if (tid < 128) {
        int o = tid - 64;
#pragma unroll
        for (int c = 0; c < 6; c++) Bw[c][o] = W1[o * 6 + c];
    }
    __syncthreads();
    int tx = tid & 15, ty = tid >> 4;
    int r4 = ty << 2, c4 = tx << 2;
    float acc[4][4] = {};
#pragma unroll
    for (int k = 0; k < 6; k++) {
        float4 a4 = *(const float4*)&Af[k][r4];
        float4 b4 = *(const float4*)&Bw[k][c4];
        float av[4] = {a4.x, a4.y, a4.z, a4.w};
        float bv[4] = {b4.x, b4.y, b4.z, b4.w};
#pragma unroll
        for (int ii = 0; ii < 4; ii++)
#pragma unroll
            for (int jj = 0; jj < 4; jj++)
                acc[ii][jj] = fmaf(av[ii], bv[jj], acc[ii][jj]);
    }
#pragma unroll
    for (int ii = 0; ii < 4; ii++)
#pragma unroll
        for (int jj = 0; jj < 4; jj++)
            g_hA[(size_t)(e0 + r4 + ii) * 64 + c4 + jj] = acc[ii][jj];
}

// ---------------------------------------------------------------------------
// Edge layers 2/4: act_slot(hA) [E,64] @ W^T [64,64] -> raw hB
// ---------------------------------------------------------------------------
__global__ __launch_bounds__(256) void k_edge64(const float* __restrict__ W, int slot) {
    __shared__ __align__(16) float As[64][68];
    __shared__ __align__(16) float Bs[64][68];
    __shared__ float sS[64], sB[64];
    int e0 = blockIdx.x << 6, tid = threadIdx.x;
    if (tid < 64) { sS[tid] = g_scale[slot * 1024 + tid]; sB[tid] = g_bias[slot * 1024 + tid]; }
    __syncthreads();
    for (int l = tid; l < 4096; l += 256) {
        int r = l >> 6, c = l & 63;
        float t = g_hA[(size_t)(e0 + r) * 64 + c] * sS[c] + sB[c];
        As[c][r] = lrelu(t);
        Bs[l & 63][l >> 6] = W[(size_t)(l >> 6) * 64 + (l & 63)];
    }
    __syncthreads();
    int tx = tid & 15, ty = tid >> 4;
    int r4 = ty << 2, c4 = tx << 2;
    float acc[4][4] = {};
#pragma unroll
    for (int k = 0; k < 64; k++) {
        float4 a4 = *(const float4*)&As[k][r4];
        float4 b4 = *(const float4*)&Bs[k][c4];
        float av[4] = {a4.x, a4.y, a4.z, a4.w};
        float bv[4] = {b4.x, b4.y, b4.z, b4.w};
#pragma unroll
        for (int ii = 0; ii < 4; ii++)
#pragma unroll
            for (int jj = 0; jj < 4; jj++)
                acc[ii][jj] = fmaf(av[ii], bv[jj], acc[ii][jj]);
    }
#pragma unroll
    for (int ii = 0; ii < 4; ii++)
#pragma unroll
        for (int jj = 0; jj < 4; jj++)
            g_hB[(size_t)(e0 + r4 + ii) * 64 + c4 + jj] = acc[ii][jj];
}

// ---------------------------------------------------------------------------
// Edge layers 3/5: gathered 128-dim edge feature [xj-xi, xi] @ W^T [64,128]
// src = x1 or x2 (already activated). Output raw -> g_hA.
// ---------------------------------------------------------------------------
__global__ __launch_bounds__(256) void k_edgeGather(const float* __restrict__ W, int srcSel) {
    __shared__ __align__(16) float As[64][68];
    __shared__ __align__(16) float Bs[64][68];
    __shared__ int sP[64], sQ[64];
    const float* src = (srcSel == 1) ? g_x1 : g_x2;
    int e0 = blockIdx.x << 6, tid = threadIdx.x;
    if (tid < 64) {
        int e = e0 + tid;
        int p = e / KNN;
        sP[tid] = p;
        sQ[tid] = (p >> 12) * NN + g_idx[e];
    }
    __syncthreads();
    int tx = tid & 15, ty = tid >> 4;
    int r4 = ty << 2, c4 = tx << 2;
    float acc[4][4] = {};
    for (int half = 0; half < 2; half++) {
        for (int l = tid; l < 4096; l += 256) {
            int c = l & 63, r = l >> 6;
            float v;
            if (half == 0)
                v = src[(size_t)sQ[r] * 64 + c] - src[(size_t)sP[r] * 64 + c];
            else
                v = src[(size_t)sP[r] * 64 + c];
            As[c][r] = v;
            Bs[l & 63][l >> 6] = W[(size_t)(l >> 6) * 128 + half * 64 + (l & 63)];
        }
        __syncthreads();
#pragma unroll
        for (int k = 0; k < 64; k++) {
            float4 a4 = *(const float4*)&As[k][r4];
            float4 b4 = *(const float4*)&Bs[k][c4];
            float av[4] = {a4.x, a4.y, a4.z, a4.w};
            float bv[4] = {b4.x, b4.y, b4.z, b4.w};
#pragma unroll
            for (int ii = 0; ii < 4; ii++)
#pragma unroll
                for (int jj = 0; jj < 4; jj++)
                    acc[ii][jj] = fmaf(av[ii], bv[jj], acc[ii][jj]);
        }
        __syncthreads();
    }
#pragma unroll
    for (int ii = 0; ii < 4; ii++)
#pragma unroll
        for (int jj = 0; jj < 4; jj++)
            g_hA[(size_t)(e0 + r4 + ii) * 64 + c4 + jj] = acc[ii][jj];
}

// ---------------------------------------------------------------------------
// Point GEMMs (layers 6/7/8). Modes:
//   0: Cin=192  A = [x1,x2,x3]               out g_h6
//   1: Cin=1216 A = [gmax(b),x1,x2,x3]       out g_h7
//   2: Cin=512  A = act_slot(g_h7)           out g_h8
// ---------------------------------------------------------------------------
__global__ __launch_bounds__(256) void k_point(const float* __restrict__ W,
                                               int Cin, int Cout, int mode,
                                               int slot, int outSel) {
    __shared__ __align__(16) float As[64][68];
    __shared__ __align__(16) float Bs[64][68];
    int c0 = blockIdx.x << 6, r0 = blockIdx.y << 6;
    int tid = threadIdx.x, tx = tid & 15, ty = tid >> 4;
    int r4 = ty << 2, c4 = tx << 2;
    int b = r0 >> 12;
    float acc[4][4] = {};
    for (int k0 = 0; k0 < Cin; k0 += 64) {
        for (int l = tid; l < 4096; l += 256) {
            int kk = l & 63, r = l >> 6;
            int c = k0 + kk, row = r0 + r;
            float v;
            if (mode == 0) {
                v = (c < 64) ? g_x1[(size_t)row * 64 + c]
                  : (c < 128) ? g_x2[(size_t)row * 64 + c - 64]
                              : g_x3[(size_t)row * 64 + c - 128];
            } else if (mode == 1) {
                if (c < 1024) v = g_gmax[b * 1024 + c];
                else {
                    int cc = c - 1024;
                    v = (cc < 64) ? g_x1[(size_t)row * 64 + cc]
                      : (cc < 128) ? g_x2[(size_t)row * 64 + cc - 64]
                                   : g_x3[(size_t)row * 64 + cc - 128];
                }
            } else {
                float raw = g_h7[(size_t)row * 512 + c];
                float t = raw * g_scale[slot * 1024 + c] + g_bias[slot * 1024 + c];
                v = lrelu(t);
            }
            As[kk][r] = v;
            Bs[l & 63][l >> 6] = W[(size_t)(c0 + (l >> 6)) * Cin + k0 + (l & 63)];
        }
        __syncthreads();
#pragma unroll
        for (int k = 0; k < 64; k++) {
            float4 a4 = *(const float4*)&As[k][r4];
            float4 b4 = *(const float4*)&Bs[k][c4];
            float av[4] = {a4.x, a4.y, a4.z, a4.w};
            float bv[4] = {b4.x, b4.y, b4.z, b4.w};
#pragma unroll
            for (int ii = 0; ii < 4; ii++)
#pragma unroll
                for (int jj = 0; jj < 4; jj++)
                    acc[ii][jj] = fmaf(av[ii], bv[jj], acc[ii][jj]);
        }
        __syncthreads();
    }
    float* out = (outSel == 0) ? g_h6 : (outSel == 1 ? g_h7 : g_h8);
#pragma unroll
    for (int ii = 0; ii < 4; ii++)
#pragma unroll
        for (int jj = 0; jj < 4; jj++)
            out[(size_t)(r0 + r4 + ii) * Cout + c0 + c4 + jj] = acc[ii][jj];
}

// ---------------------------------------------------------------------------
// BN statistics: per-channel sum / sumsq of a raw [M,C] tensor (C power of 2)
// ---------------------------------------------------------------------------
__global__ __launch_bounds__(256) void k_stats(int inSel, long long M, int C, int slot) {
    __shared__ float ss[1024], sq[1024];
    const float* h = statbuf(inSel);
    int tid = threadIdx.x;
    for (int i = tid; i < C; i += 256) { ss[i] = 0.f; sq[i] = 0.f; }
    __syncthreads();
    long long total  = M * (long long)C;
    long long stride = (long long)gridDim.x * 256;
    long long i0     = (long long)blockIdx.x * 256 + tid;
    int c0 = (int)(i0 & (long long)(C - 1));
    float s = 0.f, q = 0.f;
    for (long long i = i0; i < total; i += stride) {
        float v = h[i];
        s += v; q += v * v;
    }
    atomicAdd(&ss[c0], s);
    atomicAdd(&sq[c0], q);
    __syncthreads();
    for (int i = tid; i < C; i += 256) {
        atomicAdd(&g_sum[slot * 1024 + i], ss[i]);
        atomicAdd(&g_sumsq[slot * 1024 + i], sq[i]);
    }
}

// fold (gamma, beta, mean, var) -> per-channel scale/bias
__global__ void k_fin(int slot, int C, float invM,
                      const float* __restrict__ g, const float* __restrict__ b) {
    int c = blockIdx.x * 256 + threadIdx.x;
    if (c >= C) return;
    float mean = g_sum[slot * 1024 + c] * invM;
    float var  = g_sumsq[slot * 1024 + c] * invM - mean * mean;
    float sc   = g[c] * rsqrtf(var + EPSBN);
    g_scale[slot * 1024 + c] = sc;
    g_bias[slot * 1024 + c]  = b[c] - mean * sc;
}

// ---------------------------------------------------------------------------
// Max over k edges of act_slot(h) -> x{1,2,3}[P,64]
// ---------------------------------------------------------------------------
__global__ void k_maxe(int inSel, int slot, int outSel) {
    const float* h = (inSel == 0) ? g_hA : g_hB;
    float* out = (outSel == 1) ? g_x1 : (outSel == 2 ? g_x2 : g_x3);
    int t = blockIdx.x * 256 + threadIdx.x;
    if (t >= PT * 64) return;
    int p = t >> 6, c = t & 63;
    float sc = g_scale[slot * 1024 + c], bi = g_bias[slot * 1024 + c];
    const float* base = h + ((size_t)p * KNN) * 64 + c;
    float m = -3.0e38f;
#pragma unroll
    for (int j = 0; j < KNN; j++) {
        float v = lrelu(base[j * 64] * sc + bi);
        m = fmaxf(m, v);
    }
    out[t] = m;
}

// ---------------------------------------------------------------------------
// Global max pool over N of act_slot5(h6): partial (16 chunks) + combine
// ---------------------------------------------------------------------------
__global__ __launch_bounds__(256) void k_gmax1() {
    int b = blockIdx.y, chunk = blockIdx.x, tid = threadIdx.x;
    float m[4]  = {-3.0e38f, -3.0e38f, -3.0e38f, -3.0e38f};
    float s[4], bi[4];
#pragma unroll
    for (int u = 0; u < 4; u++) {
        int c = tid + 256 * u;
        s[u]  = g_scale[5 * 1024 + c];
        bi[u] = g_bias[5 * 1024 + c];
    }
    for (int r = 0; r < 256; r++) {
        const float* hr = g_h6 + (size_t)(b * NN + chunk * 256 + r) * 1024;
#pragma unroll
        for (int u = 0; u < 4; u++) {
            float t = lrelu(hr[tid + 256 * u] * s[u] + bi[u]);
            m[u] = fmaxf(m[u], t);
        }
    }
#pragma unroll
    for (int u = 0; u < 4; u++)
        g_gpart[(size_t)(b * 16 + chunk) * 1024 + tid + 256 * u] = m[u];
}

__global__ void k_gmax2() {
    int t = blockIdx.x * 256 + threadIdx.x;
    if (t >= BB * 1024) return;
    int b = t >> 10, c = t & 1023;
    float m = -3.0e38f;
#pragma unroll
    for (int ch = 0; ch < 16; ch++)
        m = fmaxf(m, g_gpart[(size_t)(b * 16 + ch) * 1024 + c]);
    g_gmax[t] = m;
}

// ---------------------------------------------------------------------------
// Final: out[P,9] = act_slot7(h8) @ W9^T   (no BN/act after W9)
// ---------------------------------------------------------------------------
__global__ void k_out9(const float* __restrict__ W9, float* __restrict__ out) {
    int t = blockIdx.x * 256 + threadIdx.x;
    if (t >= PT * 9) return;
    int p = t / 9, o = t - p * 9;
    const float* row = g_h8 + (size_t)p * 256;
    const float* w   = W9 + o * 256;
    float acc = 0.f;
#pragma unroll 4
    for (int k = 0; k < 256; k++) {
        float v = lrelu(row[k] * g_scale[7 * 1024 + k] + g_bias[7 * 1024 + k]);
        acc = fmaf(v, w[k], acc);
    }
    out[t] = acc;
}

// ---------------------------------------------------------------------------
// Host launcher
// ---------------------------------------------------------------------------
extern "C" void kernel_launch(void* const* d_in, const int* in_sizes, int n_in,
                              void* d_out, int out_size) {
    int base = (in_sizes[1] == 1) ? 2 : 1;
    const float* x = (const float*)d_in[0];
    const float* W[9];
    const float* G[8];
    const float* Bt[8];
    for (int i = 0; i < 9; i++) W[i] = (const float*)d_in[base + i];
    for (int i = 0; i < 8; i++) {
        G[i]  = (const float*)d_in[base + 9 + 2 * i];
        Bt[i] = (const float*)d_in[base + 10 + 2 * i];
    }
    float* out = (float*)d_out;

    const float invE = 1.f / (float)ET;
    const float invP = 1.f / (float)PT;

    k_zero<<<32, 256>>>();
    k_prep3<<<PT / 256, 256>>>(x);

    // ---- stage 1: knn on xyz, edge layers 1-2, maxpool -> x1 ----
    k_dist<3><<<dim3(64, 64, BB), 256>>>(0);
    k_topk<<<PT, 128>>>();
    k_edge1<<<ET / 64, 256>>>(W[0]);
    k_stats<<<512, 256>>>(0, (long long)ET, 64, 0);
    k_fin<<<1, 256>>>(0, 64, invE, G[0], Bt[0]);
    k_edge64<<<ET / 64, 256>>>(W[1], 0);
    k_stats<<<512, 256>>>(1, (long long)ET, 64, 1);
    k_fin<<<1, 256>>>(1, 64, invE, G[1], Bt[1]);
    k_maxe<<<PT * 64 / 256, 256>>>(1, 1, 1);

    // ---- stage 2: knn on x1, edge layers 3-4, maxpool -> x2 ----
    k_xx64<<<PT * 32 / 256, 256>>>(1);
    k_dist<64><<<dim3(64, 64, BB), 256>>>(1);
    k_topk<<<PT, 128>>>();
    k_edgeGather<<<ET / 64, 256>>>(W[2], 1);
    k_stats<<<512, 256>>>(0, (long long)ET, 64, 2);
    k_fin<<<1, 256>>>(2, 64, invE, G[2], Bt[2]);
    k_edge64<<<ET / 64, 256>>>(W[3], 2);
    k_stats<<<512, 256>>>(1, (long long)ET, 64, 3);
    k_fin<<<1, 256>>>(3, 64, invE, G[3], Bt[3]);
    k_maxe<<<PT * 64 / 256, 256>>>(1, 3, 2);

    // ---- stage 3: knn on x2, edge layer 5, maxpool -> x3 ----
    k_xx64<<<PT * 32 / 256, 256>>>(2);
    k_dist<64><<<dim3(64, 64, BB), 256>>>(2);
    k_topk<<<PT, 128>>>();
    k_edgeGather<<<ET / 64, 256>>>(W[4], 2);
    k_stats<<<512, 256>>>(0, (long long)ET, 64, 4);
    k_fin<<<1, 256>>>(4, 64, invE, G[4], Bt[4]);
    k_maxe<<<PT * 64 / 256, 256>>>(0, 4, 3);

    // ---- point layers 6-9 ----
    k_point<<<dim3(16, PT / 64), 256>>>(W[5], 192, 1024, 0, 0, 0);
    k_stats<<<512, 256>>>(2, (long long)PT, 1024, 5);
    k_fin<<<4, 256>>>(5, 1024, invP, G[5], Bt[5]);
    k_gmax1<<<dim3(16, BB), 256>>>();
    k_gmax2<<<32, 256>>>();
    k_point<<<dim3(8, PT / 64), 256>>>(W[6], 1216, 512, 1, 0, 1);
    k_stats<<<512, 256>>>(3, (long long)PT, 512, 6);
    k_fin<<<2, 256>>>(6, 512, invP, G[6], Bt[6]);
    k_point<<<dim3(4, PT / 64), 256>>>(W[7], 512, 256, 2, 6, 2);
    k_stats<<<512, 256>>>(4, (long long)PT, 256, 7);
    k_fin<<<1, 256>>>(7, 256, invP, G[7], Bt[7]);
    k_out9<<<(PT * 9 + 255) / 256, 256>>>(W[8], out);
}

// round 6
// speedup vs baseline: 1.2218x; 1.0155x over previous
#include <cuda_runtime.h>

#define KNN   20
#define BB    8
#define NN    4096
#define PT    (BB * NN)          /* 32768  points */
#define ET    (PT * KNN)         /* 655360 edges  */
#define EPSBN 1e-5f

// ---------------------------------------------------------------------------
// Static device scratch (no allocations anywhere)
// ---------------------------------------------------------------------------
static __device__ float g_feat3[PT * 3];
static __device__ float g_xx[PT];
static __device__ float g_dist[(size_t)PT * NN];        // 512 MB
static __device__ int   g_idx[ET];
static __device__ float g_hA[(size_t)ET * 64];          // 160 MB
static __device__ float g_hB[(size_t)ET * 64];          // 160 MB
static __device__ float g_x1[PT * 64];
static __device__ float g_x2[PT * 64];
static __device__ float g_x3[PT * 64];
static __device__ float g_h6[(size_t)PT * 1024];        // 128 MB
static __device__ float g_h7[(size_t)PT * 512];
static __device__ float g_h8[(size_t)PT * 256];
static __device__ float g_gpart[BB * 16 * 1024];
static __device__ float g_gmax[BB * 1024];
static __device__ float g_gcorr[BB * 512];
static __device__ float g_sum[8 * 1024];
static __device__ float g_sumsq[8 * 1024];
static __device__ float g_scale[8 * 1024];
static __device__ float g_bias[8 * 1024];

__device__ __forceinline__ float lrelu(float v) { return v > 0.f ? v : 0.2f * v; }

// ---------------------------------------------------------------------------
// Fused BN-stats epilogue for 64x64 tile GEMMs.
// acc[4][4] per thread (rows r4.., cols c4..). Per-channel sum/sumsq of the
// tile is reduced (thread -> shfl16 pair -> smem atomics) and pushed to
// g_sum/g_sumsq[slot] with 64 global atomics per CTA.
// Requires ssum/ssq zeroed before the block's first __syncthreads.
// ---------------------------------------------------------------------------
__device__ __forceinline__ void tile_bn_stats(const float acc[4][4], int tid, int c4,
                                              float* ssum, float* ssq,
                                              int slot, int cbase) {
    float ps[4], pq[4];
#pragma unroll
    for (int jj = 0; jj < 4; jj++) {
        float s = 0.f, q = 0.f;
#pragma unroll
        for (int ii = 0; ii < 4; ii++) { float v = acc[ii][jj]; s += v; q = fmaf(v, v, q); }
        ps[jj] = s; pq[jj] = q;
    }
#pragma unroll
    for (int jj = 0; jj < 4; jj++) {
        ps[jj] += __shfl_down_sync(0xffffffffu, ps[jj], 16);
        pq[jj] += __shfl_down_sync(0xffffffffu, pq[jj], 16);
    }
    if ((tid & 31) < 16) {
#pragma unroll
        for (int jj = 0; jj < 4; jj++) {
            atomicAdd(&ssum[c4 + jj], ps[jj]);
            atomicAdd(&ssq[c4 + jj], pq[jj]);
        }
    }
    __syncthreads();
    if (tid < 64) {
        atomicAdd(&g_sum[slot * 1024 + cbase + tid], ssum[tid]);
        atomicAdd(&g_sumsq[slot * 1024 + cbase + tid], ssq[tid]);
    }
}

// ---------------------------------------------------------------------------
// Zero the BN statistic accumulators (must run each launch for graph replay)
// ---------------------------------------------------------------------------
__global__ void k_zero() {
    int t = blockIdx.x * 256 + threadIdx.x;
    if (t < 8 * 1024) { g_sum[t] = 0.f; g_sumsq[t] = 0.f; }
}

// ---------------------------------------------------------------------------
// Transpose x [B,3,N] -> feat3 [P,3] and squared norms
// ---------------------------------------------------------------------------
__global__ void k_prep3(const float* __restrict__ x) {
    int p = blockIdx.x * 256 + threadIdx.x;
    if (p >= PT) return;
    int b = p >> 12, n = p & (NN - 1);
    const float* xb = x + (size_t)b * 3 * NN;
    float a0 = xb[n], a1 = xb[NN + n], a2 = xb[2 * NN + n];
    g_feat3[p * 3 + 0] = a0;
    g_feat3[p * 3 + 1] = a1;
    g_feat3[p * 3 + 2] = a2;
    g_xx[p] = a0 * a0 + a1 * a1 + a2 * a2;
}

// squared norms of [P,64] feature arrays (sel: 1 -> x1, 2 -> x2); warp per row
__global__ void k_xx64(int sel) {
    const float* f = (sel == 1) ? g_x1 : g_x2;
    int gt = blockIdx.x * 256 + threadIdx.x;
    int w = gt >> 5, lane = gt & 31;
    if (w >= PT) return;
    const float* r = f + ((size_t)w << 6);
    float v0 = r[lane], v1 = r[lane + 32];
    float s = v0 * v0 + v1 * v1;
#pragma unroll
    for (int o = 16; o; o >>= 1) s += __shfl_down_sync(0xffffffffu, s, o);
    if (lane == 0) g_xx[w] = s;
}

// ---------------------------------------------------------------------------
// Pairwise neg. squared distance (stages 2/3, C=64)
// ---------------------------------------------------------------------------
template <int C>
__global__ __launch_bounds__(256) void k_dist(int sel) {
    __shared__ __align__(16) float As[C][68];
    __shared__ __align__(16) float Bs[C][68];
    __shared__ float sxi[64], sxj[64];
    const float* f = (sel == 1) ? g_x1 : g_x2;
    int b  = blockIdx.z;
    int j0 = blockIdx.x << 6, i0 = blockIdx.y << 6;
    int tid = threadIdx.x, tx = tid & 15, ty = tid >> 4;
    int bi = b * NN + i0, bj = b * NN + j0;
    for (int l = tid; l < 64 * C; l += 256) {
        int r = l / C, c = l - r * C;
        As[c][r] = f[(size_t)(bi + r) * C + c];
        Bs[c][r] = f[(size_t)(bj + r) * C + c];
    }
    if (tid < 64) sxi[tid] = g_xx[bi + tid];
    else if (tid < 128) sxj[tid - 64] = g_xx[bj + tid - 64];
    __syncthreads();
    float acc[4][4] = {};
    int r4 = ty << 2, c4 = tx << 2;
#pragma unroll
    for (int k = 0; k < C; k++) {
        float4 a4 = *(const float4*)&As[k][r4];
        float4 b4 = *(const float4*)&Bs[k][c4];
        float av[4] = {a4.x, a4.y, a4.z, a4.w};
        float bv[4] = {b4.x, b4.y, b4.z, b4.w};
#pragma unroll
        for (int ii = 0; ii < 4; ii++)
#pragma unroll
            for (int jj = 0; jj < 4; jj++)
                acc[ii][jj] = fmaf(av[ii], bv[jj], acc[ii][jj]);
    }
#pragma unroll
    for (int ii = 0; ii < 4; ii++) {
        int i = i0 + r4 + ii;
        float xi = sxi[r4 + ii];
#pragma unroll
        for (int jj = 0; jj < 4; jj++)
            g_dist[(size_t)(b * NN + i) * NN + j0 + c4 + jj] =
                2.f * acc[ii][jj] - xi - sxj[c4 + jj];
    }
}

// ---------------------------------------------------------------------------
// Tournament-with-replacement top-K selection over per-thread 32 registers.
// ---------------------------------------------------------------------------
__device__ __forceinline__ void topk_select(float (&v)[32], int row, int tid,
                                            unsigned long long* swmax, int* sbwin) {
    unsigned mask = 0u;
    float curv = v[0];
    int   curp = 0;
#pragma unroll
    for (int i = 1; i < 32; i++)
        if (v[i] > curv) { curv = v[i]; curp = i; }

    for (int r = 0; r < KNN; r++) {
        unsigned ub = __float_as_uint(curv);
        ub = (ub & 0x80000000u) ? ~ub : (ub | 0x80000000u);
        unsigned long long key = ((unsigned long long)ub << 32) | (unsigned)tid;
#pragma unroll
        for (int o = 16; o; o >>= 1) {
            unsigned long long ok = __shfl_down_sync(0xffffffffu, key, o);
            if (ok > key) key = ok;
        }
        if ((tid & 31) == 0) swmax[tid >> 5] = key;
        __syncthreads();
        if (tid == 0) {
            unsigned long long best = swmax[0];
#pragma unroll
            for (int w = 1; w < 4; w++)
                if (swmax[w] > best) best = swmax[w];
            *sbwin = (int)(unsigned)best;
        }
        __syncthreads();
        if (tid == *sbwin) {
            g_idx[(size_t)row * KNN + r] = tid * 32 + curp;
            mask |= 1u << curp;
            curv = -3.0e38f;
            curp = 0;
#pragma unroll
            for (int i = 0; i < 32; i++) {
                bool ok = !(mask & (1u << i)) && (v[i] > curv);
                if (ok) { curv = v[i]; curp = i; }
            }
        }
    }
}

// stages 2/3: read precomputed g_dist
__global__ __launch_bounds__(128) void k_topk() {
    __shared__ unsigned long long swmax[4];
    __shared__ int sbwin;
    int row = blockIdx.x;
    int tid = threadIdx.x;
    const float4* d4 = (const float4*)(g_dist + (size_t)row * NN) + tid * 8;
    float v[32];
#pragma unroll
    for (int q = 0; q < 8; q++) {
        float4 t4 = d4[q];
        v[4 * q + 0] = t4.x; v[4 * q + 1] = t4.y;
        v[4 * q + 2] = t4.z; v[4 * q + 3] = t4.w;
    }
    topk_select(v, row, tid, swmax, &sbwin);
}

// stage 1: compute 3-D distances inline (no dist matrix round-trip)
__global__ __launch_bounds__(128) void k_topk3() {
    __shared__ unsigned long long swmax[4];
    __shared__ int sbwin;
    int row = blockIdx.x;
    int tid = threadIdx.x;
    int b = row >> 12;
    float xi0 = g_feat3[row * 3], xi1 = g_feat3[row * 3 + 1], xi2 = g_feat3[row * 3 + 2];
    float xxi = g_xx[row];
    const float* fj = g_feat3 + ((size_t)(b * NN) + tid * 32) * 3;
    float v[32];
#pragma unroll
    for (int i = 0; i < 32; i++) {
        float a0 = fj[i * 3], a1 = fj[i * 3 + 1], a2 = fj[i * 3 + 2];
        float dot = fmaf(a0, xi0, fmaf(a1, xi1, a2 * xi2));
        float xxj = fmaf(a0, a0, fmaf(a1, a1, a2 * a2));
        v[i] = 2.f * dot - xxi - xxj;
    }
    topk_select(v, row, tid, swmax, &sbwin);
}

// ---------------------------------------------------------------------------
// Edge layer 1: gather [xj-xi, xi] (6 dims) @ W1^T -> raw hA [E,64] + stats(0)
// ---------------------------------------------------------------------------
__global__ __launch_bounds__(256) void k_edge1(const float* __restrict__ W1) {
    __shared__ __align__(16) float Af[6][68];
    __shared__ __align__(16) float Bw[6][68];
    __shared__ float ssum[64], ssq[64];
    int e0 = blockIdx.x << 6, tid = threadIdx.x;
    if (tid < 64) { ssum[tid] = 0.f; ssq[tid] = 0.f; }
    if (tid < 64) {
        int e = e0 + tid;
        int p = e / KNN;
        int q = (p >> 12) * NN + g_idx[e];
        float p0 = g_feat3[p * 3], p1 = g_feat3[p * 3 + 1], p2 = g_feat3[p * 3 + 2];
        float q0 = g_feat3[q * 3], q1 = g_feat3[q * 3 + 1], q2 = g_feat3[q * 3 + 2];
        Af[0][tid] = q0 - p0; Af[1][tid] = q1 - p1; Af[2][tid] = q2 - p2;
        Af[3][tid] = p0;      Af[4][tid] = p1;      Af[5][tid] = p2;
    } else if (tid < 128) {
        int o = tid - 64;
#pragma unroll
        for (int c = 0; c < 6; c++) Bw[c][o] = W1[o * 6 + c];
    }
    __syncthreads();
    int tx = tid & 15, ty = tid >> 4;
    int r4 = ty << 2, c4 = tx << 2;
    float acc[4][4] = {};
#pragma unroll
    for (int k = 0; k < 6; k++) {
        float4 a4 = *(const float4*)&Af[k][r4];
        float4 b4 = *(const float4*)&Bw[k][c4];
        float av[4] = {a4.x, a4.y, a4.z, a4.w};
        float bv[4] = {b4.x, b4.y, b4.z, b4.w};
#pragma unroll
        for (int ii = 0; ii < 4; ii++)
#pragma unroll
            for (int jj = 0; jj < 4; jj++)
                acc[ii][jj] = fmaf(av[ii], bv[jj], acc[ii][jj]);
    }
#pragma unroll
    for (int ii = 0; ii < 4; ii++)
#pragma unroll
        for (int jj = 0; jj < 4; jj++)
            g_hA[(size_t)(e0 + r4 + ii) * 64 + c4 + jj] = acc[ii][jj];
    tile_bn_stats(acc, tid, c4, ssum, ssq, 0, 0);
}

// ---------------------------------------------------------------------------
// Edge layers 2/4: act_aslot(hA) [E,64] @ W^T [64,64] -> raw hB + stats(oslot)
// ---------------------------------------------------------------------------
__global__ __launch_bounds__(256) void k_edge64(const float* __restrict__ W,
                                                int aslot, int oslot) {
    __shared__ __align__(16) float As[64][68];
    __shared__ __align__(16) float Bs[64][68];
    __shared__ float sS[64], sB[64];
    __shared__ float ssum[64], ssq[64];
    int e0 = blockIdx.x << 6, tid = threadIdx.x;
    if (tid < 64) {
        sS[tid] = g_scale[aslot * 1024 + tid];
        sB[tid] = g_bias[aslot * 1024 + tid];
        ssum[tid] = 0.f; ssq[tid] = 0.f;
    }
    __syncthreads();
    for (int l = tid; l < 4096; l += 256) {
        int r = l >> 6, c = l & 63;
        float t = g_hA[(size_t)(e0 + r) * 64 + c] * sS[c] + sB[c];
        As[c][r] = lrelu(t);
        Bs[l & 63][l >> 6] = W[(size_t)(l >> 6) * 64 + (l & 63)];
    }
    __syncthreads();
    int tx = tid & 15, ty = tid >> 4;
    int r4 = ty << 2, c4 = tx << 2;
    float acc[4][4] = {};
#pragma unroll
    for (int k = 0; k < 64; k++) {
        float4 a4 = *(const float4*)&As[k][r4];
        float4 b4 = *(const float4*)&Bs[k][c4];
        float av[4] = {a4.x, a4.y, a4.z, a4.w};
        float bv[4] = {b4.x, b4.y, b4.z, b4.w};
#pragma unroll
        for (int ii = 0; ii < 4; ii++)
#pragma unroll
            for (int jj = 0; jj < 4; jj++)
                acc[ii][jj] = fmaf(av[ii], bv[jj], acc[ii][jj]);
    }
#pragma unroll
    for (int ii = 0; ii < 4; ii++)
#pragma unroll
        for (int jj = 0; jj < 4; jj++)
            g_hB[(size_t)(e0 + r4 + ii) * 64 + c4 + jj] = acc[ii][jj];
    tile_bn_stats(acc, tid, c4, ssum, ssq, oslot, 0);
}

// ---------------------------------------------------------------------------
// Edge layers 3/5: gathered 128-dim edge feature @ W^T [64,128] -> hA + stats
// ---------------------------------------------------------------------------
__global__ __launch_bounds__(256) void k_edgeGather(const float* __restrict__ W,
                                                    int srcSel, int oslot) {
    __shared__ __align__(16) float As[64][68];
    __shared__ __align__(16) float Bs[64][68];
    __shared__ int sP[64], sQ[64];
    __shared__ float ssum[64], ssq[64];
    const float* src = (srcSel == 1) ? g_x1 : g_x2;
    int e0 = blockIdx.x << 6, tid = threadIdx.x;
    if (tid < 64) {
        int e = e0 + tid;
        int p = e / KNN;
        sP[tid] = p;
        sQ[tid] = (p >> 12) * NN + g_idx[e];
        ssum[tid] = 0.f; ssq[tid] = 0.f;
    }
    __syncthreads();
    int tx = tid & 15, ty = tid >> 4;
    int r4 = ty << 2, c4 = tx << 2;
    float acc[4][4] = {};
    for (int half = 0; half < 2; half++) {
        for (int l = tid; l < 4096; l += 256) {
            int c = l & 63, r = l >> 6;
            float v;
            if (half == 0)
                v = src[(size_t)sQ[r] * 64 + c] - src[(size_t)sP[r] * 64 + c];
            else
                v = src[(size_t)sP[r] * 64 + c];
            As[c][r] = v;
            Bs[l & 63][l >> 6] = W[(size_t)(l >> 6) * 128 + half * 64 + (l & 63)];
        }
        __syncthreads();
#pragma unroll
        for (int k = 0; k < 64; k++) {
            float4 a4 = *(const float4*)&As[k][r4];
            float4 b4 = *(const float4*)&Bs[k][c4];
            float av[4] = {a4.x, a4.y, a4.z, a4.w};
            float bv[4] = {b4.x, b4.y, b4.z, b4.w};
#pragma unroll
            for (int ii = 0; ii < 4; ii++)
#pragma unroll
                for (int jj = 0; jj < 4; jj++)
                    acc[ii][jj] = fmaf(av[ii], bv[jj], acc[ii][jj]);
        }
        __syncthreads();
    }
#pragma unroll
    for (int ii = 0; ii < 4; ii++)
#pragma unroll
        for (int jj = 0; jj < 4; jj++)
            g_hA[(size_t)(e0 + r4 + ii) * 64 + c4 + jj] = acc[ii][jj];
    tile_bn_stats(acc, tid, c4, ssum, ssq, oslot, 0);
}

// ---------------------------------------------------------------------------
// Point GEMMs. Modes:
//   0: A=[x1,x2,x3](192) @ W6                -> h6 (stats slot 5)
//   1: A=[x1,x2,x3](192) @ W7[:,1024:] + gcorr -> h7 (stats slot 6)
//   2: A=act6(h7)(512)   @ W8                -> h8 (stats slot 7)
// ---------------------------------------------------------------------------
__global__ __launch_bounds__(256) void k_point(const float* __restrict__ W,
                                               int Cin, int Cout, int wstride,
                                               int woff, int mode, int aslot,
                                               int outSel) {
    __shared__ __align__(16) float As[64][68];
    __shared__ __align__(16) float Bs[64][68];
    __shared__ float ssum[64], ssq[64];
    int c0 = blockIdx.x << 6, r0 = blockIdx.y << 6;
    int tid = threadIdx.x, tx = tid & 15, ty = tid >> 4;
    int r4 = ty << 2, c4 = tx << 2;
    int b = r0 >> 12;
    if (tid < 64) { ssum[tid] = 0.f; ssq[tid] = 0.f; }
    float acc[4][4] = {};
    for (int k0 = 0; k0 < Cin; k0 += 64) {
        for (int l = tid; l < 4096; l += 256) {
            int kk = l & 63, r = l >> 6;
            int c = k0 + kk, row = r0 + r;
            float v;
            if (mode != 2) {
                v = (c < 64) ? g_x1[(size_t)row * 64 + c]
                  : (c < 128) ? g_x2[(size_t)row * 64 + c - 64]
                              : g_x3[(size_t)row * 64 + c - 128];
            } else {
                float raw = g_h7[(size_t)row * 512 + c];
                float t = raw * g_scale[aslot * 1024 + c] + g_bias[aslot * 1024 + c];
                v = lrelu(t);
            }
            As[kk][r] = v;
            Bs[l & 63][l >> 6] = W[(size_t)(c0 + (l >> 6)) * wstride + woff + k0 + (l & 63)];
        }
        __syncthreads();
#pragma unroll
        for (int k = 0; k < 64; k++) {
            float4 a4 = *(const float4*)&As[k][r4];
            float4 b4 = *(const float4*)&Bs[k][c4];
            float av[4] = {a4.x, a4.y, a4.z, a4.w};
            float bv[4] = {b4.x, b4.y, b4.z, b4.w};
#pragma unroll
            for (int ii = 0; ii < 4; ii++)
#pragma unroll
                for (int jj = 0; jj < 4; jj++)
                    acc[ii][jj] = fmaf(av[ii], bv[jj], acc[ii][jj]);
        }
        __syncthreads();
    }
    if (mode == 1) {
#pragma unroll
        for (int jj = 0; jj < 4; jj++) {
            float gc = g_gcorr[b * 512 + c0 + c4 + jj];
#pragma unroll
            for (int ii = 0; ii < 4; ii++) acc[ii][jj] += gc;
        }
    }
    float* out = (outSel == 0) ? g_h6 : (outSel == 1 ? g_h7 : g_h8);
#pragma unroll
    for (int ii = 0; ii < 4; ii++)
#pragma unroll
        for (int jj = 0; jj < 4; jj++)
            out[(size_t)(r0 + r4 + ii) * Cout + c0 + c4 + jj] = acc[ii][jj];
    tile_bn_stats(acc, tid, c4, ssum, ssq, 5 + outSel, c0);
}

// gcorr[b,o] = sum_c gmax[b,c] * W7[o,c]  (c < 1024); warp per output
__global__ void k_gcorr(const float* __restrict__ W7) {
    int b = blockIdx.y;
    int o = blockIdx.x * 8 + (threadIdx.x >> 5);
    int lane = threadIdx.x & 31;
    const float* gm = g_gmax + b * 1024;
    const float* w  = W7 + (size_t)o * 1216;
    float s = 0.f;
#pragma unroll 8
    for (int k = lane; k < 1024; k += 32) s = fmaf(gm[k], w[k], s);
#pragma unroll
    for (int off = 16; off; off >>= 1) s += __shfl_down_sync(0xffffffffu, s, off);
    if (lane == 0) g_gcorr[b * 512 + o] = s;
}

// fold (gamma, beta, mean, var) -> per-channel scale/bias
__global__ void k_fin(int slot, int C, float invM,
                      const float* __restrict__ g, const float* __restrict__ b) {
    int c = blockIdx.x * 256 + threadIdx.x;
    if (c >= C) return;
    float mean = g_sum[slot * 1024 + c] * invM;
    float var  = g_sumsq[slot * 1024 + c] * invM - mean * mean;
    float sc   = g[c] * rsqrtf(var + EPSBN);
    g_scale[slot * 1024 + c] = sc;
    g_bias[slot * 1024 + c]  = b[c] - mean * sc;
}

// ---------------------------------------------------------------------------
// Max over k edges of act_slot(h) -> x{1,2,3}[P,64]
// ---------------------------------------------------------------------------
__global__ void k_maxe(int inSel, int slot, int outSel) {
    const float* h = (inSel == 0) ? g_hA : g_hB;
    float* out = (outSel == 1) ? g_x1 : (outSel == 2 ? g_x2 : g_x3);
    int t = blockIdx.x * 256 + threadIdx.x;
    if (t >= PT * 64) return;
    int p = t >> 6, c = t & 63;
    float sc = g_scale[slot * 1024 + c], bi = g_bias[slot * 1024 + c];
    const float* base = h + ((size_t)p * KNN) * 64 + c;
    float m = -3.0e38f;
#pragma unroll
    for (int j = 0; j < KNN; j++) {
        float v = lrelu(base[j * 64] * sc + bi);
        m = fmaxf(m, v);
    }
    out[t] = m;
}

// ---------------------------------------------------------------------------
// Global max pool over N of act5(h6): partial (16 chunks) + combine
// ---------------------------------------------------------------------------
__global__ __launch_bounds__(256) void k_gmax1() {
    int b = blockIdx.y, chunk = blockIdx.x, tid = threadIdx.x;
    float m[4]  = {-3.0e38f, -3.0e38f, -3.0e38f, -3.0e38f};
    float s[4], bi[4];
#pragma unroll
    for (int u = 0; u < 4; u++) {
        int c = tid + 256 * u;
        s[u]  = g_scale[5 * 1024 + c];
        bi[u] = g_bias[5 * 1024 + c];
    }
    for (int r = 0; r < 256; r++) {
        const float* hr = g_h6 + (size_t)(b * NN + chunk * 256 + r) * 1024;
#pragma unroll
        for (int u = 0; u < 4; u++) {
            float t = lrelu(hr[tid + 256 * u] * s[u] + bi[u]);
            m[u] = fmaxf(m[u], t);
        }
    }
#pragma unroll
    for (int u = 0; u < 4; u++)
        g_gpart[(size_t)(b * 16 + chunk) * 1024 + tid + 256 * u] = m[u];
}

__global__ void k_gmax2() {
    int t = blockIdx.x * 256 + threadIdx.x;
    if (t >= BB * 1024) return;
    int b = t >> 10, c = t & 1023;
    float m = -3.0e38f;
#pragma unroll
    for (int ch = 0; ch < 16; ch++)
        m = fmaxf(m, g_gpart[(size_t)(b * 16 + ch) * 1024 + c]);
    g_gmax[t] = m;
}

// ---------------------------------------------------------------------------
// Final: out[P,9] = act7(h8) @ W9^T
// ---------------------------------------------------------------------------
__global__ void k_out9(const float* __restrict__ W9, float* __restrict__ out) {
    int t = blockIdx.x * 256 + threadIdx.x;
    if (t >= PT * 9) return;
    int p = t / 9, o = t - p * 9;
    const float* row = g_h8 + (size_t)p * 256;
    const float* w   = W9 + o * 256;
    float acc = 0.f;
#pragma unroll 4
    for (int k = 0; k < 256; k++) {
        float v = lrelu(row[k] * g_scale[7 * 1024 + k] + g_bias[7 * 1024 + k]);
        acc = fmaf(v, w[k], acc);
    }
    out[t] = acc;
}

// ---------------------------------------------------------------------------
// Host launcher
// ---------------------------------------------------------------------------
extern "C" void kernel_launch(void* const* d_in, const int* in_sizes, int n_in,
                              void* d_out, int out_size) {
    int base = (in_sizes[1] == 1) ? 2 : 1;
    const float* x = (const float*)d_in[0];
    const float* W[9];
    const float* G[8];
    const float* Bt[8];
    for (int i = 0; i < 9; i++) W[i] = (const float*)d_in[base + i];
    for (int i = 0; i < 8; i++) {
        G[i]  = (const float*)d_in[base + 9 + 2 * i];
        Bt[i] = (const float*)d_in[base + 10 + 2 * i];
    }
    float* out = (float*)d_out;

    const float invE = 1.f / (float)ET;
    const float invP = 1.f / (float)PT;

    k_zero<<<32, 256>>>();
    k_prep3<<<PT / 256, 256>>>(x);

    // ---- stage 1: fused knn on xyz, edge layers 1-2, maxpool -> x1 ----
    k_topk3<<<PT, 128>>>();
    k_edge1<<<ET / 64, 256>>>(W[0]);
    k_fin<<<1, 256>>>(0, 64, invE, G[0], Bt[0]);
    k_edge64<<<ET / 64, 256>>>(W[1], 0, 1);
    k_fin<<<1, 256>>>(1, 64, invE, G[1], Bt[1]);
    k_maxe<<<PT * 64 / 256, 256>>>(1, 1, 1);

    // ---- stage 2: knn on x1, edge layers 3-4, maxpool -> x2 ----
    k_xx64<<<PT * 32 / 256, 256>>>(1);
    k_dist<64><<<dim3(64, 64, BB), 256>>>(1);
    k_topk<<<PT, 128>>>();
    k_edgeGather<<<ET / 64, 256>>>(W[2], 1, 2);
    k_fin<<<1, 256>>>(2, 64, invE, G[2], Bt[2]);
    k_edge64<<<ET / 64, 256>>>(W[3], 2, 3);
    k_fin<<<1, 256>>>(3, 64, invE, G[3], Bt[3]);
    k_maxe<<<PT * 64 / 256, 256>>>(1, 3, 2);

    // ---- stage 3: knn on x2, edge layer 5, maxpool -> x3 ----
    k_xx64<<<PT * 32 / 256, 256>>>(2);
    k_dist<64><<<dim3(64, 64, BB), 256>>>(2);
    k_topk<<<PT, 128>>>();
    k_edgeGather<<<ET / 64, 256>>>(W[4], 2, 4);
    k_fin<<<1, 256>>>(4, 64, invE, G[4], Bt[4]);
    k_maxe<<<PT * 64 / 256, 256>>>(0, 4, 3);

    // ---- point layers 6-9 ----
    k_point<<<dim3(16, PT / 64), 256>>>(W[5], 192, 1024, 192, 0, 0, 0, 0);
    k_fin<<<4, 256>>>(5, 1024, invP, G[5], Bt[5]);
    k_gmax1<<<dim3(16, BB), 256>>>();
    k_gmax2<<<32, 256>>>();
    k_gcorr<<<dim3(64, BB), 256>>>(W[6]);
    k_point<<<dim3(8, PT / 64), 256>>>(W[6], 192, 512, 1216, 1024, 1, 0, 1);
    k_fin<<<2, 256>>>(6, 512, invP, G[6], Bt[6]);
    k_point<<<dim3(4, PT / 64), 256>>>(W[7], 512, 256, 512, 0, 2, 6, 2);
    k_fin<<<1, 256>>>(7, 256, invP, G[7], Bt[7]);
    k_out9<<<(PT * 9 + 255) / 256, 256>>>(W[8], out);
}

// round 7
// speedup vs baseline: 1.3137x; 1.0752x over previous
#include <cuda_runtime.h>

#define KNN   20
#define BB    8
#define NN    4096
#define PT    (BB * NN)          /* 32768  points */
#define ET    (PT * KNN)         /* 655360 edges  */
#define EPSBN 1e-5f

// ---------------------------------------------------------------------------
// Static device scratch (no allocations anywhere)
// ---------------------------------------------------------------------------
static __device__ float g_feat3[PT * 3];
static __device__ float g_xx[PT];
static __device__ float g_dist[(size_t)PT * NN];        // 512 MB
static __device__ int   g_idx[ET];
static __device__ float g_hA[(size_t)ET * 64];          // 160 MB
static __device__ float g_hB[(size_t)ET * 64];          // 160 MB
static __device__ float g_x1[PT * 64];
static __device__ float g_x2[PT * 64];
static __device__ float g_x3[PT * 64];
static __device__ float g_h6[(size_t)PT * 1024];        // 128 MB
static __device__ float g_h7[(size_t)PT * 512];
static __device__ float g_h8[(size_t)PT * 256];
static __device__ float g_gpart[BB * 16 * 1024];
static __device__ float g_gmax[BB * 1024];
static __device__ float g_gcorr[BB * 512];
static __device__ float g_sum[8 * 1024];
static __device__ float g_sumsq[8 * 1024];
static __device__ float g_scale[8 * 1024];
static __device__ float g_bias[8 * 1024];

__device__ __forceinline__ float lrelu(float v) { return v > 0.f ? v : 0.2f * v; }

// monotone float -> unsigned transform (preserves total order)
__device__ __forceinline__ unsigned ford(float f) {
    unsigned u = __float_as_uint(f);
    return (u & 0x80000000u) ? ~u : (u | 0x80000000u);
}

// ---------------------------------------------------------------------------
// Fused BN-stats epilogue for 64x64 tile GEMMs.
// ---------------------------------------------------------------------------
__device__ __forceinline__ void tile_bn_stats(const float acc[4][4], int tid, int c4,
                                              float* ssum, float* ssq,
                                              int slot, int cbase) {
    float ps[4], pq[4];
#pragma unroll
    for (int jj = 0; jj < 4; jj++) {
        float s = 0.f, q = 0.f;
#pragma unroll
        for (int ii = 0; ii < 4; ii++) { float v = acc[ii][jj]; s += v; q = fmaf(v, v, q); }
        ps[jj] = s; pq[jj] = q;
    }
#pragma unroll
    for (int jj = 0; jj < 4; jj++) {
        ps[jj] += __shfl_down_sync(0xffffffffu, ps[jj], 16);
        pq[jj] += __shfl_down_sync(0xffffffffu, pq[jj], 16);
    }
    if ((tid & 31) < 16) {
#pragma unroll
        for (int jj = 0; jj < 4; jj++) {
            atomicAdd(&ssum[c4 + jj], ps[jj]);
            atomicAdd(&ssq[c4 + jj], pq[jj]);
        }
    }
    __syncthreads();
    if (tid < 64) {
        atomicAdd(&g_sum[slot * 1024 + cbase + tid], ssum[tid]);
        atomicAdd(&g_sumsq[slot * 1024 + cbase + tid], ssq[tid]);
    }
}

// ---------------------------------------------------------------------------
// Zero BN statistic accumulators (graph-replay safe)
// ---------------------------------------------------------------------------
__global__ void k_zero() {
    int t = blockIdx.x * 256 + threadIdx.x;
    if (t < 8 * 1024) { g_sum[t] = 0.f; g_sumsq[t] = 0.f; }
}

// ---------------------------------------------------------------------------
// Transpose x [B,3,N] -> feat3 [P,3] and squared norms
// ---------------------------------------------------------------------------
__global__ void k_prep3(const float* __restrict__ x) {
    int p = blockIdx.x * 256 + threadIdx.x;
    if (p >= PT) return;
    int b = p >> 12, n = p & (NN - 1);
    const float* xb = x + (size_t)b * 3 * NN;
    float a0 = xb[n], a1 = xb[NN + n], a2 = xb[2 * NN + n];
    g_feat3[p * 3 + 0] = a0;
    g_feat3[p * 3 + 1] = a1;
    g_feat3[p * 3 + 2] = a2;
    g_xx[p] = a0 * a0 + a1 * a1 + a2 * a2;
}

// squared norms of [P,64] feature arrays; warp per row
__global__ void k_xx64(int sel) {
    const float* f = (sel == 1) ? g_x1 : g_x2;
    int gt = blockIdx.x * 256 + threadIdx.x;
    int w = gt >> 5, lane = gt & 31;
    if (w >= PT) return;
    const float* r = f + ((size_t)w << 6);
    float v0 = r[lane], v1 = r[lane + 32];
    float s = v0 * v0 + v1 * v1;
#pragma unroll
    for (int o = 16; o; o >>= 1) s += __shfl_down_sync(0xffffffffu, s, o);
    if (lane == 0) g_xx[w] = s;
}

// ---------------------------------------------------------------------------
// Pairwise neg. squared distance, C=64: 128x128 tile, 8x8 per thread,
// k-sliced 16 at a time. dist[b,i,j] = 2<xi,xj> - |xi|^2 - |xj|^2
// grid (32, 32, B), 256 threads
// ---------------------------------------------------------------------------
__global__ __launch_bounds__(256) void k_dist128(int sel) {
    __shared__ __align__(16) float As[16][132];
    __shared__ __align__(16) float Bs[16][132];
    __shared__ float sxi[128], sxj[128];
    const float* f = (sel == 1) ? g_x1 : g_x2;
    int b  = blockIdx.z;
    int j0 = blockIdx.x << 7, i0 = blockIdx.y << 7;
    int tid = threadIdx.x, tx = tid & 15, ty = tid >> 4;
    int r8 = ty << 3, c8 = tx << 3;
    int bi = b * NN + i0, bj = b * NN + j0;
    if (tid < 128) sxi[tid] = g_xx[bi + tid];
    else           sxj[tid - 128] = g_xx[bj + tid - 128];
    float acc[8][8] = {};
    for (int k0 = 0; k0 < 64; k0 += 16) {
        __syncthreads();
#pragma unroll
        for (int l = tid; l < 512; l += 256) {
            int r = l >> 2, kq = (l & 3) << 2;
            float4 av = *(const float4*)&f[(size_t)(bi + r) * 64 + k0 + kq];
            As[kq + 0][r] = av.x; As[kq + 1][r] = av.y;
            As[kq + 2][r] = av.z; As[kq + 3][r] = av.w;
            float4 bv = *(const float4*)&f[(size_t)(bj + r) * 64 + k0 + kq];
            Bs[kq + 0][r] = bv.x; Bs[kq + 1][r] = bv.y;
            Bs[kq + 2][r] = bv.z; Bs[kq + 3][r] = bv.w;
        }
        __syncthreads();
#pragma unroll
        for (int k = 0; k < 16; k++) {
            float a[8], bb[8];
            *(float4*)&a[0]  = *(const float4*)&As[k][r8];
            *(float4*)&a[4]  = *(const float4*)&As[k][r8 + 4];
            *(float4*)&bb[0] = *(const float4*)&Bs[k][c8];
            *(float4*)&bb[4] = *(const float4*)&Bs[k][c8 + 4];
#pragma unroll
            for (int ii = 0; ii < 8; ii++)
#pragma unroll
                for (int jj = 0; jj < 8; jj++)
                    acc[ii][jj] = fmaf(a[ii], bb[jj], acc[ii][jj]);
        }
    }
#pragma unroll
    for (int ii = 0; ii < 8; ii++) {
        float xi = sxi[r8 + ii];
        float o[8];
#pragma unroll
        for (int jj = 0; jj < 8; jj++)
            o[jj] = 2.f * acc[ii][jj] - xi - sxj[c8 + jj];
        float* dst = &g_dist[(size_t)(b * NN + i0 + r8 + ii) * NN + j0 + c8];
        *(float4*)&dst[0] = *(float4*)&o[0];
        *(float4*)&dst[4] = *(float4*)&o[4];
    }
}

// ---------------------------------------------------------------------------
// Top-K: warp-local tournaments (no block syncs) + single-warp merge.
// 128 threads/row. Warp w owns cols [w*1024, w*1024+1024), lane-interleaved:
// pos (q,t) of lane  ->  j = w*1024 + q*128 + lane*4 + t.
// Phase 1: each warp extracts its top-20 into smem candidates (shfl only).
// Phase 2: warp 0 merges 80 candidates -> global top-20.
// ---------------------------------------------------------------------------
__device__ __forceinline__ void topk_phase1(float (&v)[32], int lane, int w,
                                            int wb, unsigned* cvu, int* ci) {
    float curv = v[0];
    int   curp = 0;
#pragma unroll
    for (int i = 1; i < 32; i++)
        if (v[i] > curv) { curv = v[i]; curp = i; }
    unsigned mask = 0u;
    for (int r = 0; r < KNN; r++) {
        unsigned long long key =
            ((unsigned long long)ford(curv) << 32) | (unsigned)(lane * 32 + curp);
#pragma unroll
        for (int o = 16; o; o >>= 1) {
            unsigned long long ok = __shfl_xor_sync(0xffffffffu, key, o);
            if (ok > key) key = ok;
        }
        int ws = (int)(key & 1023u);
        int wlane = ws >> 5, wpos = ws & 31;
        if (lane == r) {
            cvu[w * 20 + r] = (unsigned)(key >> 32);
            ci[w * 20 + r]  = wb + ((wpos >> 2) << 7) + (wlane << 2) + (wpos & 3);
        }
        if (lane == wlane) {
            mask |= 1u << wpos;
            curv = -3.0e38f; curp = 0;
#pragma unroll
            for (int i = 0; i < 32; i++) {
                bool ok = !((mask >> i) & 1u) && (v[i] > curv);
                if (ok) { curv = v[i]; curp = i; }
            }
        }
    }
}

__device__ __forceinline__ void topk_phase2(int row, int lane, unsigned* cvu, int* ci) {
    unsigned uv[3];
#pragma unroll
    for (int u = 0; u < 3; u++) {
        int s = lane + 32 * u;
        uv[u] = (s < 80) ? cvu[s] : 0u;
    }
    unsigned bcur = uv[0]; int bu = 0;
    if (uv[1] > bcur) { bcur = uv[1]; bu = 1; }
    if (uv[2] > bcur) { bcur = uv[2]; bu = 2; }
    for (int r = 0; r < KNN; r++) {
        unsigned long long key =
            ((unsigned long long)bcur << 32) | (unsigned)(lane + 32 * bu);
#pragma unroll
        for (int o = 16; o; o >>= 1) {
            unsigned long long ok = __shfl_xor_sync(0xffffffffu, key, o);
            if (ok > key) key = ok;
        }
        int ws = (int)(key & 127u);
        if (lane == 0) g_idx[(size_t)row * KNN + r] = ci[ws];
        if (lane == (ws & 31)) {
            uv[ws >> 5] = 0u;
            bcur = uv[0]; bu = 0;
            if (uv[1] > bcur) { bcur = uv[1]; bu = 1; }
            if (uv[2] > bcur) { bcur = uv[2]; bu = 2; }
        }
    }
}

// stages 2/3: read precomputed g_dist
__global__ __launch_bounds__(128) void k_topk() {
    __shared__ unsigned cvu[80];
    __shared__ int      ci[80];
    int row = blockIdx.x;
    int tid = threadIdx.x, lane = tid & 31, w = tid >> 5;
    int wb = w * 1024;
    const float4* base = (const float4*)(g_dist + (size_t)row * NN + wb);
    float v[32];
#pragma unroll
    for (int q = 0; q < 8; q++) {
        float4 t4 = base[q * 32 + lane];
        v[4 * q + 0] = t4.x; v[4 * q + 1] = t4.y;
        v[4 * q + 2] = t4.z; v[4 * q + 3] = t4.w;
    }
    topk_phase1(v, lane, w, wb, cvu, ci);
    __syncthreads();
    if (w == 0) topk_phase2(row, lane, cvu, ci);
}

// stage 1: compute 3-D distances inline (no dist matrix round-trip)
__global__ __launch_bounds__(128) void k_topk3() {
    __shared__ unsigned cvu[80];
    __shared__ int      ci[80];
    int row = blockIdx.x;
    int tid = threadIdx.x, lane = tid & 31, w = tid >> 5;
    int b = row >> 12;
    int wb = w * 1024;
    float xi0 = g_feat3[row * 3], xi1 = g_feat3[row * 3 + 1], xi2 = g_feat3[row * 3 + 2];
    float xxi = g_xx[row];
    float v[32];
#pragma unroll
    for (int q = 0; q < 8; q++) {
        int j0 = wb + q * 128 + lane * 4;
        const float4* fp = (const float4*)(g_feat3 + ((size_t)(b * NN) + j0) * 3);
        float4 f0 = fp[0], f1 = fp[1], f2 = fp[2];
        float arr[12] = {f0.x, f0.y, f0.z, f0.w, f1.x, f1.y, f1.z, f1.w,
                         f2.x, f2.y, f2.z, f2.w};
#pragma unroll
        for (int t = 0; t < 4; t++) {
            float a0 = arr[t * 3], a1 = arr[t * 3 + 1], a2 = arr[t * 3 + 2];
            float dot = fmaf(a0, xi0, fmaf(a1, xi1, a2 * xi2));
            float xxj = fmaf(a0, a0, fmaf(a1, a1, a2 * a2));
            v[4 * q + t] = 2.f * dot - xxi - xxj;
        }
    }
    topk_phase1(v, lane, w, wb, cvu, ci);
    __syncthreads();
    if (w == 0) topk_phase2(row, lane, cvu, ci);
}

// ---------------------------------------------------------------------------
// Edge layer 1: gather [xj-xi, xi] (6 dims) @ W1^T -> raw hA [E,64] + stats(0)
// ---------------------------------------------------------------------------
__global__ __launch_bounds__(256) void k_edge1(const float* __restrict__ W1) {
    __shared__ __align__(16) float Af[6][68];
    __shared__ __align__(16) float Bw[6][68];
    __shared__ float ssum[64], ssq[64];
    int e0 = blockIdx.x << 6, tid = threadIdx.x;
    if (tid < 64) { ssum[tid] = 0.f; ssq[tid] = 0.f; }
    if (tid < 64) {
        int e = e0 + tid;
        int p = e / KNN;
        int q = (p >> 12) * NN + g_idx[e];
        float p0 = g_feat3[p * 3], p1 = g_feat3[p * 3 + 1], p2 = g_feat3[p * 3 + 2];
        float q0 = g_feat3[q * 3], q1 = g_feat3[q * 3 + 1], q2 = g_feat3[q * 3 + 2];
        Af[0][tid] = q0 - p0; Af[1][tid] = q1 - p1; Af[2][tid] = q2 - p2;
        Af[3][tid] = p0;      Af[4][tid] = p1;      Af[5][tid] = p2;
    } else if (tid < 128) {
        int o = tid - 64;
#pragma unroll
        for (int c = 0; c < 6; c++) Bw[c][o] = W1[o * 6 + c];
    }
    __syncthreads();
    int tx = tid & 15, ty = tid >> 4;
    int r4 = ty << 2, c4 = tx << 2;
    float acc[4][4] = {};
#pragma unroll
    for (int k = 0; k < 6; k++) {
        float4 a4 = *(const float4*)&Af[k][r4];
        float4 b4 = *(const float4*)&Bw[k][c4];
        float av[4] = {a4.x, a4.y, a4.z, a4.w};
        float bv[4] = {b4.x, b4.y, b4.z, b4.w};
#pragma unroll
        for (int ii = 0; ii < 4; ii++)
#pragma unroll
            for (int jj = 0; jj < 4; jj++)
                acc[ii][jj] = fmaf(av[ii], bv[jj], acc[ii][jj]);
    }
#pragma unroll
    for (int ii = 0; ii < 4; ii++)
#pragma unroll
        for (int jj = 0; jj < 4; jj++)
            g_hA[(size_t)(e0 + r4 + ii) * 64 + c4 + jj] = acc[ii][jj];
    tile_bn_stats(acc, tid, c4, ssum, ssq, 0, 0);
}

// ---------------------------------------------------------------------------
// Edge layers 2/4: act_aslot(hA) [E,64] @ W^T [64,64] -> raw hB + stats(oslot)
// ---------------------------------------------------------------------------
__global__ __launch_bounds__(256) void k_edge64(const float* __restrict__ W,
                                                int aslot, int oslot) {
    __shared__ __align__(16) float As[64][68];
    __shared__ __align__(16) float Bs[64][68];
    __shared__ float sS[64], sB[64];
    __shared__ float ssum[64], ssq[64];
    int e0 = blockIdx.x << 6, tid = threadIdx.x;
    if (tid < 64) {
        sS[tid] = g_scale[aslot * 1024 + tid];
        sB[tid] = g_bias[aslot * 1024 + tid];
        ssum[tid] = 0.f; ssq[tid] = 0.f;
    }
    __syncthreads();
    for (int l = tid; l < 4096; l += 256) {
        int r = l >> 6, c = l & 63;
        float t = g_hA[(size_t)(e0 + r) * 64 + c] * sS[c] + sB[c];
        As[c][r] = lrelu(t);
        Bs[l & 63][l >> 6] = W[(size_t)(l >> 6) * 64 + (l & 63)];
    }
    __syncthreads();
    int tx = tid & 15, ty = tid >> 4;
    int r4 = ty << 2, c4 = tx << 2;
    float acc[4][4] = {};
#pragma unroll
    for (int k = 0; k < 64; k++) {
        float4 a4 = *(const float4*)&As[k][r4];
        float4 b4 = *(const float4*)&Bs[k][c4];
        float av[4] = {a4.x, a4.y, a4.z, a4.w};
        float bv[4] = {b4.x, b4.y, b4.z, b4.w};
#pragma unroll
        for (int ii = 0; ii < 4; ii++)
#pragma unroll
            for (int jj = 0; jj < 4; jj++)
                acc[ii][jj] = fmaf(av[ii], bv[jj], acc[ii][jj]);
    }
#pragma unroll
    for (int ii = 0; ii < 4; ii++)
#pragma unroll
        for (int jj = 0; jj < 4; jj++)
            g_hB[(size_t)(e0 + r4 + ii) * 64 + c4 + jj] = acc[ii][jj];
    tile_bn_stats(acc, tid, c4, ssum, ssq, oslot, 0);
}

// ---------------------------------------------------------------------------
// Edge layers 3/5: gathered 128-dim edge feature @ W^T [64,128] -> hA + stats
// ---------------------------------------------------------------------------
__global__ __launch_bounds__(256) void k_edgeGather(const float* __restrict__ W,
                                                    int srcSel, int oslot) {
    __shared__ __align__(16) float As[64][68];
    __shared__ __align__(16) float Bs[64][68];
    __shared__ int sP[64], sQ[64];
    __shared__ float ssum[64], ssq[64];
    const float* src = (srcSel == 1) ? g_x1 : g_x2;
    int e0 = blockIdx.x << 6, tid = threadIdx.x;
    if (tid < 64) {
        int e = e0 + tid;
        int p = e / KNN;
        sP[tid] = p;
        sQ[tid] = (p >> 12) * NN + g_idx[e];
        ssum[tid] = 0.f; ssq[tid] = 0.f;
    }
    __syncthreads();
    int tx = tid & 15, ty = tid >> 4;
    int r4 = ty << 2, c4 = tx << 2;
    float acc[4][4] = {};
    for (int half = 0; half < 2; half++) {
        for (int l = tid; l < 4096; l += 256) {
            int c = l & 63, r = l >> 6;
            float v;
            if (half == 0)
                v = src[(size_t)sQ[r] * 64 + c] - src[(size_t)sP[r] * 64 + c];
            else
                v = src[(size_t)sP[r] * 64 + c];
            As[c][r] = v;
            Bs[l & 63][l >> 6] = W[(size_t)(l >> 6) * 128 + half * 64 + (l & 63)];
        }
        __syncthreads();
#pragma unroll
        for (int k = 0; k < 64; k++) {
            float4 a4 = *(const float4*)&As[k][r4];
            float4 b4 = *(const float4*)&Bs[k][c4];
            float av[4] = {a4.x, a4.y, a4.z, a4.w};
            float bv[4] = {b4.x, b4.y, b4.z, b4.w};
#pragma unroll
            for (int ii = 0; ii < 4; ii++)
#pragma unroll
                for (int jj = 0; jj < 4; jj++)
                    acc[ii][jj] = fmaf(av[ii], bv[jj], acc[ii][jj]);
        }
        __syncthreads();
    }
#pragma unroll
    for (int ii = 0; ii < 4; ii++)
#pragma unroll
        for (int jj = 0; jj < 4; jj++)
            g_hA[(size_t)(e0 + r4 + ii) * 64 + c4 + jj] = acc[ii][jj];
    tile_bn_stats(acc, tid, c4, ssum, ssq, oslot, 0);
}

// ---------------------------------------------------------------------------
// Point GEMMs. Modes:
//   0: A=[x1,x2,x3](192) @ W6                  -> h6 (stats slot 5)
//   1: A=[x1,x2,x3](192) @ W7[:,1024:] + gcorr -> h7 (stats slot 6)
//   2: A=act6(h7)(512)   @ W8                  -> h8 (stats slot 7)
// ---------------------------------------------------------------------------
__global__ __launch_bounds__(256) void k_point(const float* __restrict__ W,
                                               int Cin, int Cout, int wstride,
                                               int woff, int mode, int aslot,
                                               int outSel) {
    __shared__ __align__(16) float As[64][68];
    __shared__ __align__(16) float Bs[64][68];
    __shared__ float ssum[64], ssq[64];
    int c0 = blockIdx.x << 6, r0 = blockIdx.y << 6;
    int tid = threadIdx.x, tx = tid & 15, ty = tid >> 4;
    int r4 = ty << 2, c4 = tx << 2;
    int b = r0 >> 12;
    if (tid < 64) { ssum[tid] = 0.f; ssq[tid] = 0.f; }
    float acc[4][4] = {};
    for (int k0 = 0; k0 < Cin; k0 += 64) {
        for (int l = tid; l < 4096; l += 256) {
            int kk = l & 63, r = l >> 6;
            int c = k0 + kk, row = r0 + r;
            float v;
            if (mode != 2) {
                v = (c < 64) ? g_x1[(size_t)row * 64 + c]
                  : (c < 128) ? g_x2[(size_t)row * 64 + c - 64]
                              : g_x3[(size_t)row * 64 + c - 128];
            } else {
                float raw = g_h7[(size_t)row * 512 + c];
                float t = raw * g_scale[aslot * 1024 + c] + g_bias[aslot * 1024 + c];
                v = lrelu(t);
            }
            As[kk][r] = v;
            Bs[l & 63][l >> 6] = W[(size_t)(c0 + (l >> 6)) * wstride + woff + k0 + (l & 63)];
        }
        __syncthreads();
#pragma unroll
        for (int k = 0; k < 64; k++) {
            float4 a4 = *(const float4*)&As[k][r4];
            float4 b4 = *(const float4*)&Bs[k][c4];
            float av[4] = {a4.x, a4.y, a4.z, a4.w};
            float bv[4] = {b4.x, b4.y, b4.z, b4.w};
#pragma unroll
            for (int ii = 0; ii < 4; ii++)
#pragma unroll
                for (int jj = 0; jj < 4; jj++)
                    acc[ii][jj] = fmaf(av[ii], bv[jj], acc[ii][jj]);
        }
        __syncthreads();
    }
    if (mode == 1) {
#pragma unroll
        for (int jj = 0; jj < 4; jj++) {
            float gc = g_gcorr[b * 512 + c0 + c4 + jj];
#pragma unroll
            for (int ii = 0; ii < 4; ii++) acc[ii][jj] += gc;
        }
    }
    float* out = (outSel == 0) ? g_h6 : (outSel == 1 ? g_h7 : g_h8);
#pragma unroll
    for (int ii = 0; ii < 4; ii++)
#pragma unroll
        for (int jj = 0; jj < 4; jj++)
            out[(size_t)(r0 + r4 + ii) * Cout + c0 + c4 + jj] = acc[ii][jj];
    tile_bn_stats(acc, tid, c4, ssum, ssq, 5 + outSel, c0);
}

// gcorr[b,o] = sum_c gmax[b,c] * W7[o,c]  (c < 1024); warp per output
__global__ void k_gcorr(const float* __restrict__ W7) {
    int b = blockIdx.y;
    int o = blockIdx.x * 8 + (threadIdx.x >> 5);
    int lane = threadIdx.x & 31;
    const float* gm = g_gmax + b * 1024;
    const float* w  = W7 + (size_t)o * 1216;
    float s = 0.f;
#pragma unroll 8
    for (int k = lane; k < 1024; k += 32) s = fmaf(gm[k], w[k], s);
#pragma unroll
    for (int off = 16; off; off >>= 1) s += __shfl_down_sync(0xffffffffu, s, off);
    if (lane == 0) g_gcorr[b * 512 + o] = s;
}

// fold (gamma, beta, mean, var) -> per-channel scale/bias
__global__ void k_fin(int slot, int C, float invM,
                      const float* __restrict__ g, const float* __restrict__ b) {
    int c = blockIdx.x * 256 + threadIdx.x;
    if (c >= C) return;
    float mean = g_sum[slot * 1024 + c] * invM;
    float var  = g_sumsq[slot * 1024 + c] * invM - mean * mean;
    float sc   = g[c] * rsqrtf(var + EPSBN);
    g_scale[slot * 1024 + c] = sc;
    g_bias[slot * 1024 + c]  = b[c] - mean * sc;
}

// ---------------------------------------------------------------------------
// Max over k edges of act_slot(h) -> x{1,2,3}[P,64]
// ---------------------------------------------------------------------------
__global__ void k_maxe(int inSel, int slot, int outSel) {
    const float* h = (inSel == 0) ? g_hA : g_hB;
    float* out = (outSel == 1) ? g_x1 : (outSel == 2 ? g_x2 : g_x3);
    int t = blockIdx.x * 256 + threadIdx.x;
    if (t >= PT * 64) return;
    int p = t >> 6, c = t & 63;
    float sc = g_scale[slot * 1024 + c], bi = g_bias[slot * 1024 + c];
    const float* base = h + ((size_t)p * KNN) * 64 + c;
    float m = -3.0e38f;
#pragma unroll
    for (int j = 0; j < KNN; j++) {
        float v = lrelu(base[j * 64] * sc + bi);
        m = fmaxf(m, v);
    }
    out[t] = m;
}

// ---------------------------------------------------------------------------
// Global max pool over N of act5(h6): partial (16 chunks) + combine
// ---------------------------------------------------------------------------
__global__ __launch_bounds__(256) void k_gmax1() {
    int b = blockIdx.y, chunk = blockIdx.x, tid = threadIdx.x;
    float m[4]  = {-3.0e38f, -3.0e38f, -3.0e38f, -3.0e38f};
    float s[4], bi[4];
#pragma unroll
    for (int u = 0; u < 4; u++) {
        int c = tid + 256 * u;
        s[u]  = g_scale[5 * 1024 + c];
        bi[u] = g_bias[5 * 1024 + c];
    }
    for (int r = 0; r < 256; r++) {
        const float* hr = g_h6 + (size_t)(b * NN + chunk * 256 + r) * 1024;
#pragma unroll
        for (int u = 0; u < 4; u++) {
            float t = lrelu(hr[tid + 256 * u] * s[u] + bi[u]);
            m[u] = fmaxf(m[u], t);
        }
    }
#pragma unroll
    for (int u = 0; u < 4; u++)
        g_gpart[(size_t)(b * 16 + chunk) * 1024 + tid + 256 * u] = m[u];
}

__global__ void k_gmax2() {
    int t = blockIdx.x * 256 + threadIdx.x;
    if (t >= BB * 1024) return;
    int b = t >> 10, c = t & 1023;
    float m = -3.0e38f;
#pragma unroll
    for (int ch = 0; ch < 16; ch++)
        m = fmaxf(m, g_gpart[(size_t)(b * 16 + ch) * 1024 + c]);
    g_gmax[t] = m;
}

// ---------------------------------------------------------------------------
// Final: out[P,9] = act7(h8) @ W9^T
// ---------------------------------------------------------------------------
__global__ void k_out9(const float* __restrict__ W9, float* __restrict__ out) {
    int t = blockIdx.x * 256 + threadIdx.x;
    if (t >= PT * 9) return;
    int p = t / 9, o = t - p * 9;
    const float* row = g_h8 + (size_t)p * 256;
    const float* w   = W9 + o * 256;
    float acc = 0.f;
#pragma unroll 4
    for (int k = 0; k < 256; k++) {
        float v = lrelu(row[k] * g_scale[7 * 1024 + k] + g_bias[7 * 1024 + k]);
        acc = fmaf(v, w[k], acc);
    }
    out[t] = acc;
}

// ---------------------------------------------------------------------------
// Host launcher
// ---------------------------------------------------------------------------
extern "C" void kernel_launch(void* const* d_in, const int* in_sizes, int n_in,
                              void* d_out, int out_size) {
    int base = (in_sizes[1] == 1) ? 2 : 1;
    const float* x = (const float*)d_in[0];
    const float* W[9];
    const float* G[8];
    const float* Bt[8];
    for (int i = 0; i < 9; i++) W[i] = (const float*)d_in[base + i];
    for (int i = 0; i < 8; i++) {
        G[i]  = (const float*)d_in[base + 9 + 2 * i];
        Bt[i] = (const float*)d_in[base + 10 + 2 * i];
    }
    float* out = (float*)d_out;

    const float invE = 1.f / (float)ET;
    const float invP = 1.f / (float)PT;

    k_zero<<<32, 256>>>();
    k_prep3<<<PT / 256, 256>>>(x);

    // ---- stage 1: fused knn on xyz, edge layers 1-2, maxpool -> x1 ----
    k_topk3<<<PT, 128>>>();
    k_edge1<<<ET / 64, 256>>>(W[0]);
    k_fin<<<1, 256>>>(0, 64, invE, G[0], Bt[0]);
    k_edge64<<<ET / 64, 256>>>(W[1], 0, 1);
    k_fin<<<1, 256>>>(1, 64, invE, G[1], Bt[1]);
    k_maxe<<<PT * 64 / 256, 256>>>(1, 1, 1);

    // ---- stage 2: knn on x1, edge layers 3-4, maxpool -> x2 ----
    k_xx64<<<PT * 32 / 256, 256>>>(1);
    k_dist128<<<dim3(32, 32, BB), 256>>>(1);
    k_topk<<<PT, 128>>>();
    k_edgeGather<<<ET / 64, 256>>>(W[2], 1, 2);
    k_fin<<<1, 256>>>(2, 64, invE, G[2], Bt[2]);
    k_edge64<<<ET / 64, 256>>>(W[3], 2, 3);
    k_fin<<<1, 256>>>(3, 64, invE, G[3], Bt[3]);
    k_maxe<<<PT * 64 / 256, 256>>>(1, 3, 2);

    // ---- stage 3: knn on x2, edge layer 5, maxpool -> x3 ----
    k_xx64<<<PT * 32 / 256, 256>>>(2);
    k_dist128<<<dim3(32, 32, BB), 256>>>(2);
    k_topk<<<PT, 128>>>();
    k_edgeGather<<<ET / 64, 256>>>(W[4], 2, 4);
    k_fin<<<1, 256>>>(4, 64, invE, G[4], Bt[4]);
    k_maxe<<<PT * 64 / 256, 256>>>(0, 4, 3);

    // ---- point layers 6-9 ----
    k_point<<<dim3(16, PT / 64), 256>>>(W[5], 192, 1024, 192, 0, 0, 0, 0);
    k_fin<<<4, 256>>>(5, 1024, invP, G[5], Bt[5]);
    k_gmax1<<<dim3(16, BB), 256>>>();
    k_gmax2<<<32, 256>>>();
    k_gcorr<<<dim3(64, BB), 256>>>(W[6]);
    k_point<<<dim3(8, PT / 64), 256>>>(W[6], 192, 512, 1216, 1024, 1, 0, 1);
    k_fin<<<2, 256>>>(6, 512, invP, G[6], Bt[6]);
    k_point<<<dim3(4, PT / 64), 256>>>(W[7], 512, 256, 512, 0, 2, 6, 2);
    k_fin<<<1, 256>>>(7, 256, invP, G[7], Bt[7]);
    k_out9<<<(PT * 9 + 255) / 256, 256>>>(W[8], out);
}

// round 9
// speedup vs baseline: 1.4682x; 1.1177x over previous
#include <cuda_runtime.h>

#define KNN   20
#define BB    8
#define NN    4096
#define PT    (BB * NN)          /* 32768  points */
#define ET    (PT * KNN)         /* 655360 edges  */
#define EPSBN 1e-5f

// ---------------------------------------------------------------------------
// Static device scratch (no allocations anywhere)
// ---------------------------------------------------------------------------
static __device__ float  g_feat3[PT * 3];
static __device__ float  g_xx[PT];
static __device__ float  g_dist[(size_t)PT * NN];        // 512 MB
static __device__ int    g_idx[ET];
static __device__ float  g_hA[(size_t)ET * 64];          // 160 MB
static __device__ float  g_hB[(size_t)ET * 64];          // 160 MB
static __device__ float  g_x1[PT * 64];
static __device__ float  g_x2[PT * 64];
static __device__ float  g_x3[PT * 64];
static __device__ float  g_h6[(size_t)PT * 1024];        // 128 MB
static __device__ float  g_h7[(size_t)PT * 512];
static __device__ float  g_h8[(size_t)PT * 256];
static __device__ float  g_gpart[BB * 16 * 1024];
static __device__ float  g_gmax[BB * 1024];
static __device__ float  g_gcorr[BB * 512];
static __device__ double g_sum[8 * 1024];
static __device__ double g_sumsq[8 * 1024];
static __device__ float  g_scale[8 * 1024];
static __device__ float  g_bias[8 * 1024];

__device__ __forceinline__ float lrelu(float v) { return v > 0.f ? v : 0.2f * v; }

// monotone float -> unsigned transform (preserves total order)
__device__ __forceinline__ unsigned ford(float f) {
    unsigned u = __float_as_uint(f);
    return (u & 0x80000000u) ? ~u : (u | 0x80000000u);
}

// ---------------------------------------------------------------------------
// Zero BN statistic accumulators (graph-replay safe)
// ---------------------------------------------------------------------------
__global__ void k_zero() {
    int t = blockIdx.x * 256 + threadIdx.x;
    if (t < 8 * 1024) { g_sum[t] = 0.0; g_sumsq[t] = 0.0; }
}

// ---------------------------------------------------------------------------
// Transpose x [B,3,N] -> feat3 [P,3] and squared norms
// ---------------------------------------------------------------------------
__global__ void k_prep3(const float* __restrict__ x) {
    int p = blockIdx.x * 256 + threadIdx.x;
    if (p >= PT) return;
    int b = p >> 12, n = p & (NN - 1);
    const float* xb = x + (size_t)b * 3 * NN;
    float a0 = xb[n], a1 = xb[NN + n], a2 = xb[2 * NN + n];
    g_feat3[p * 3 + 0] = a0;
    g_feat3[p * 3 + 1] = a1;
    g_feat3[p * 3 + 2] = a2;
    g_xx[p] = a0 * a0 + a1 * a1 + a2 * a2;
}

// squared norms of [P,64] feature arrays; warp per row
__global__ void k_xx64(int sel) {
    const float* f = (sel == 1) ? g_x1 : g_x2;
    int gt = blockIdx.x * 256 + threadIdx.x;
    int w = gt >> 5, lane = gt & 31;
    if (w >= PT) return;
    const float* r = f + ((size_t)w << 6);
    float v0 = r[lane], v1 = r[lane + 32];
    float s = v0 * v0 + v1 * v1;
#pragma unroll
    for (int o = 16; o; o >>= 1) s += __shfl_down_sync(0xffffffffu, s, o);
    if (lane == 0) g_xx[w] = s;
}

// ---------------------------------------------------------------------------
// Pairwise neg. squared distance, C=64, SYMMETRIC upper-triangle tiles.
// Transposed store subtracts the ROW's own norm first so dist[j,i] is
// bitwise identical to a row-major computation (near-tie kNN stability).
// grid (528, B), 256 threads, 8x8 per thread, k-sliced 16
// ---------------------------------------------------------------------------
__global__ __launch_bounds__(256) void k_dist128sym(int sel) {
    __shared__ __align__(16) float As[16][132];
    __shared__ __align__(16) float Bs[16][132];
    __shared__ float sxi[128], sxj[128];
    const float* f = (sel == 1) ? g_x1 : g_x2;
    int b = blockIdx.y;
    int rem = blockIdx.x, ti = 0;
    while (rem >= 32 - ti) { rem -= 32 - ti; ti++; }
    int tj = ti + rem;
    int i0 = ti << 7, j0 = tj << 7;
    int tid = threadIdx.x, tx = tid & 15, ty = tid >> 4;
    int r8 = ty << 3, c8 = tx << 3;
    int bi = b * NN + i0, bj = b * NN + j0;
    if (tid < 128) sxi[tid] = g_xx[bi + tid];
    else           sxj[tid - 128] = g_xx[bj + tid - 128];
    float acc[8][8] = {};
    for (int k0 = 0; k0 < 64; k0 += 16) {
        __syncthreads();
#pragma unroll
        for (int l = tid; l < 512; l += 256) {
            int r = l >> 2, kq = (l & 3) << 2;
            float4 av = *(const float4*)&f[(size_t)(bi + r) * 64 + k0 + kq];
            As[kq + 0][r] = av.x; As[kq + 1][r] = av.y;
            As[kq + 2][r] = av.z; As[kq + 3][r] = av.w;
            float4 bv = *(const float4*)&f[(size_t)(bj + r) * 64 + k0 + kq];
            Bs[kq + 0][r] = bv.x; Bs[kq + 1][r] = bv.y;
            Bs[kq + 2][r] = bv.z; Bs[kq + 3][r] = bv.w;
        }
        __syncthreads();
#pragma unroll
        for (int k = 0; k < 16; k++) {
            float a[8], bb[8];
            *(float4*)&a[0]  = *(const float4*)&As[k][r8];
            *(float4*)&a[4]  = *(const float4*)&As[k][r8 + 4];
            *(float4*)&bb[0] = *(const float4*)&Bs[k][c8];
            *(float4*)&bb[4] = *(const float4*)&Bs[k][c8 + 4];
#pragma unroll
            for (int ii = 0; ii < 8; ii++)
#pragma unroll
                for (int jj = 0; jj < 8; jj++)
                    acc[ii][jj] = fmaf(a[ii], bb[jj], acc[ii][jj]);
        }
    }
    // i-rows: dist[i,j] = (2*acc - xxi) - xxj
#pragma unroll
    for (int ii = 0; ii < 8; ii++) {
        float xi = sxi[r8 + ii];
        float o[8];
#pragma unroll
        for (int jj = 0; jj < 8; jj++)
            o[jj] = 2.f * acc[ii][jj] - xi - sxj[c8 + jj];
        float* dst = &g_dist[(size_t)(b * NN + i0 + r8 + ii) * NN + j0 + c8];
        *(float4*)&dst[0] = *(float4*)&o[0];
        *(float4*)&dst[4] = *(float4*)&o[4];
    }
    // j-rows (transposed): dist[j,i] = (2*acc - xxj) - xxi  (row norm FIRST)
    if (ti != tj) {
#pragma unroll
        for (int jj = 0; jj < 8; jj++) {
            float xj = sxj[c8 + jj];
            float o[8];
#pragma unroll
            for (int ii = 0; ii < 8; ii++)
                o[ii] = 2.f * acc[ii][jj] - xj - sxi[r8 + ii];
            float* dst = &g_dist[(size_t)(b * NN + j0 + c8 + jj) * NN + i0 + r8];
            *(float4*)&dst[0] = *(float4*)&o[0];
            *(float4*)&dst[4] = *(float4*)&o[4];
        }
    }
}

// ---------------------------------------------------------------------------
// Top-K: warp-local tournaments + single-warp merge (exact selection).
// ---------------------------------------------------------------------------
__device__ __forceinline__ void topk_phase1(float (&v)[32], int lane, int w,
                                            int wb, unsigned* cvu, int* ci) {
    float curv = v[0];
    int   curp = 0;
#pragma unroll
    for (int i = 1; i < 32; i++)
        if (v[i] > curv) { curv = v[i]; curp = i; }
    unsigned mask = 0u;
    for (int r = 0; r < KNN; r++) {
        unsigned long long key =
            ((unsigned long long)ford(curv) << 32) | (unsigned)(lane * 32 + curp);
#pragma unroll
        for (int o = 16; o; o >>= 1) {
            unsigned long long ok = __shfl_xor_sync(0xffffffffu, key, o);
            if (ok > key) key = ok;
        }
        int ws = (int)(key & 1023u);
        int wlane = ws >> 5, wpos = ws & 31;
        if (lane == r) {
            cvu[w * 20 + r] = (unsigned)(key >> 32);
            ci[w * 20 + r]  = wb + ((wpos >> 2) << 7) + (wlane << 2) + (wpos & 3);
        }
        if (lane == wlane) {
            mask |= 1u << wpos;
            curv = -3.0e38f; curp = 0;
#pragma unroll
            for (int i = 0; i < 32; i++) {
                bool ok = !((mask >> i) & 1u) && (v[i] > curv);
                if (ok) { curv = v[i]; curp = i; }
            }
        }
    }
}

__device__ __forceinline__ void topk_phase2(int row, int lane, unsigned* cvu, int* ci) {
    unsigned uv[3];
#pragma unroll
    for (int u = 0; u < 3; u++) {
        int s = lane + 32 * u;
        uv[u] = (s < 80) ? cvu[s] : 0u;
    }
    unsigned bcur = uv[0]; int bu = 0;
    if (uv[1] > bcur) { bcur = uv[1]; bu = 1; }
    if (uv[2] > bcur) { bcur = uv[2]; bu = 2; }
    for (int r = 0; r < KNN; r++) {
        unsigned long long key =
            ((unsigned long long)bcur << 32) | (unsigned)(lane + 32 * bu);
#pragma unroll
        for (int o = 16; o; o >>= 1) {
            unsigned long long ok = __shfl_xor_sync(0xffffffffu, key, o);
            if (ok > key) key = ok;
        }
        int ws = (int)(key & 127u);
        if (lane == 0) g_idx[(size_t)row * KNN + r] = ci[ws];
        if (lane == (ws & 31)) {
            uv[ws >> 5] = 0u;
            bcur = uv[0]; bu = 0;
            if (uv[1] > bcur) { bcur = uv[1]; bu = 1; }
            if (uv[2] > bcur) { bcur = uv[2]; bu = 2; }
        }
    }
}

// stages 2/3: read precomputed g_dist
__global__ __launch_bounds__(128) void k_topk() {
    __shared__ unsigned cvu[80];
    __shared__ int      ci[80];
    int row = blockIdx.x;
    int tid = threadIdx.x, lane = tid & 31, w = tid >> 5;
    int wb = w * 1024;
    const float4* base = (const float4*)(g_dist + (size_t)row * NN + wb);
    float v[32];
#pragma unroll
    for (int q = 0; q < 8; q++) {
        float4 t4 = base[q * 32 + lane];
        v[4 * q + 0] = t4.x; v[4 * q + 1] = t4.y;
        v[4 * q + 2] = t4.z; v[4 * q + 3] = t4.w;
    }
    topk_phase1(v, lane, w, wb, cvu, ci);
    __syncthreads();
    if (w == 0) topk_phase2(row, lane, cvu, ci);
}

// stage 1: compute 3-D distances inline (no dist matrix round-trip)
__global__ __launch_bounds__(128) void k_topk3() {
    __shared__ unsigned cvu[80];
    __shared__ int      ci[80];
    int row = blockIdx.x;
    int tid = threadIdx.x, lane = tid & 31, w = tid >> 5;
    int b = row >> 12;
    int wb = w * 1024;
    float xi0 = g_feat3[row * 3], xi1 = g_feat3[row * 3 + 1], xi2 = g_feat3[row * 3 + 2];
    float xxi = g_xx[row];
    float v[32];
#pragma unroll
    for (int q = 0; q < 8; q++) {
        int j0 = wb + q * 128 + lane * 4;
        const float4* fp = (const float4*)(g_feat3 + ((size_t)(b * NN) + j0) * 3);
        float4 f0 = fp[0], f1 = fp[1], f2 = fp[2];
        float arr[12] = {f0.x, f0.y, f0.z, f0.w, f1.x, f1.y, f1.z, f1.w,
                         f2.x, f2.y, f2.z, f2.w};
#pragma unroll
        for (int t = 0; t < 4; t++) {
            float a0 = arr[t * 3], a1 = arr[t * 3 + 1], a2 = arr[t * 3 + 2];
            float dot = fmaf(a0, xi0, fmaf(a1, xi1, a2 * xi2));
            float xxj = fmaf(a0, a0, fmaf(a1, a1, a2 * a2));
            v[4 * q + t] = 2.f * dot - xxi - xxj;
        }
    }
    topk_phase1(v, lane, w, wb, cvu, ci);
    __syncthreads();
    if (w == 0) topk_phase2(row, lane, cvu, ci);
}

// ---------------------------------------------------------------------------
// Edge layer 1: gather [xj-xi, xi] (6 dims) @ W1^T -> raw hA [E,64] + stats(0)
// ---------------------------------------------------------------------------
__global__ __launch_bounds__(256) void k_edge1(const float* __restrict__ W1) {
    __shared__ __align__(16) float Af[6][68];
    __shared__ __align__(16) float Bw[6][68];
    __shared__ double ssum[64], ssq[64];
    int e0 = blockIdx.x << 6, tid = threadIdx.x;
    if (tid < 64) { ssum[tid] = 0.0; ssq[tid] = 0.0; }
    if (tid < 64) {
        int e = e0 + tid;
        int p = e / KNN;
        int q = (p >> 12) * NN + g_idx[e];
        float p0 = g_feat3[p * 3], p1 = g_feat3[p * 3 + 1], p2 = g_feat3[p * 3 + 2];
        float q0 = g_feat3[q * 3], q1 = g_feat3[q * 3 + 1], q2 = g_feat3[q * 3 + 2];
        Af[0][tid] = q0 - p0; Af[1][tid] = q1 - p1; Af[2][tid] = q2 - p2;
        Af[3][tid] = p0;      Af[4][tid] = p1;      Af[5][tid] = p2;
    } else if (tid < 128) {
        int o = tid - 64;
#pragma unroll
        for (int c = 0; c < 6; c++) Bw[c][o] = W1[o * 6 + c];
    }
    __syncthreads();
    int tx = tid & 15, ty = tid >> 4;
    int r4 = ty << 2, c4 = tx << 2;
    float acc[4][4] = {};
#pragma unroll
    for (int k = 0; k < 6; k++) {
        float4 a4 = *(const float4*)&Af[k][r4];
        float4 b4 = *(const float4*)&Bw[k][c4];
        float av[4] = {a4.x, a4.y, a4.z, a4.w};
        float bv[4] = {b4.x, b4.y, b4.z, b4.w};
#pragma unroll
        for (int ii = 0; ii < 4; ii++)
#pragma unroll
            for (int jj = 0; jj < 4; jj++)
                acc[ii][jj] = fmaf(av[ii], bv[jj], acc[ii][jj]);
    }
#pragma unroll
    for (int ii = 0; ii < 4; ii++)
#pragma unroll
        for (int jj = 0; jj < 4; jj++)
            g_hA[(size_t)(e0 + r4 + ii) * 64 + c4 + jj] = acc[ii][jj];
#pragma unroll
    for (int jj = 0; jj < 4; jj++) {
        float s = 0.f, q = 0.f;
#pragma unroll
        for (int ii = 0; ii < 4; ii++) { float v = acc[ii][jj]; s += v; q = fmaf(v, v, q); }
        atomicAdd(&ssum[c4 + jj], (double)s);
        atomicAdd(&ssq[c4 + jj], (double)q);
    }
    __syncthreads();
    if (tid < 64) {
        atomicAdd(&g_sum[tid], ssum[tid]);
        atomicAdd(&g_sumsq[tid], ssq[tid]);
    }
}

// ---------------------------------------------------------------------------
// Edge layers 2/4: act_aslot(hA)[E,64] @ W^T[64,64] -> hB + stats(oslot)
// 128-row tile, 8x4 per thread, k-sliced 16
// ---------------------------------------------------------------------------
__global__ __launch_bounds__(256) void k_edge128(const float* __restrict__ W,
                                                 int aslot, int oslot) {
    __shared__ __align__(16) float As[16][132];
    __shared__ __align__(16) float Bs[16][68];
    __shared__ float sS[64], sB[64];
    __shared__ double ssum[64], ssq[64];
    int e0 = blockIdx.x << 7, tid = threadIdx.x;
    if (tid < 64) {
        sS[tid] = g_scale[aslot * 1024 + tid];
        sB[tid] = g_bias[aslot * 1024 + tid];
        ssum[tid] = 0.0; ssq[tid] = 0.0;
    }
    int tx = tid & 15, ty = tid >> 4;
    int r8 = ty << 3, c4 = tx << 2;
    float acc[8][4] = {};
    for (int k0 = 0; k0 < 64; k0 += 16) {
        __syncthreads();
#pragma unroll
        for (int l = tid; l < 512; l += 256) {
            int r = l >> 2, kq = (l & 3) << 2;
            int c = k0 + kq;
            float4 av = *(const float4*)&g_hA[(size_t)(e0 + r) * 64 + c];
            As[kq + 0][r] = lrelu(av.x * sS[c + 0] + sB[c + 0]);
            As[kq + 1][r] = lrelu(av.y * sS[c + 1] + sB[c + 1]);
            As[kq + 2][r] = lrelu(av.z * sS[c + 2] + sB[c + 2]);
            As[kq + 3][r] = lrelu(av.w * sS[c + 3] + sB[c + 3]);
        }
        {
            int r = tid >> 2, kq = (tid & 3) << 2;
            float4 bv = *(const float4*)&W[(size_t)r * 64 + k0 + kq];
            Bs[kq + 0][r] = bv.x; Bs[kq + 1][r] = bv.y;
            Bs[kq + 2][r] = bv.z; Bs[kq + 3][r] = bv.w;
        }
        __syncthreads();
#pragma unroll
        for (int k = 0; k < 16; k++) {
            float a[8], bb[4];
            *(float4*)&a[0]  = *(const float4*)&As[k][r8];
            *(float4*)&a[4]  = *(const float4*)&As[k][r8 + 4];
            *(float4*)&bb[0] = *(const float4*)&Bs[k][c4];
#pragma unroll
            for (int ii = 0; ii < 8; ii++)
#pragma unroll
                for (int jj = 0; jj < 4; jj++)
                    acc[ii][jj] = fmaf(a[ii], bb[jj], acc[ii][jj]);
        }
    }
#pragma unroll
    for (int ii = 0; ii < 8; ii++)
        *(float4*)&g_hB[(size_t)(e0 + r8 + ii) * 64 + c4] = *(float4*)&acc[ii][0];
#pragma unroll
    for (int jj = 0; jj < 4; jj++) {
        float s = 0.f, q = 0.f;
#pragma unroll
        for (int ii = 0; ii < 8; ii++) { float v = acc[ii][jj]; s += v; q = fmaf(v, v, q); }
        atomicAdd(&ssum[c4 + jj], (double)s);
        atomicAdd(&ssq[c4 + jj], (double)q);
    }
    __syncthreads();
    if (tid < 64) {
        atomicAdd(&g_sum[oslot * 1024 + tid], ssum[tid]);
        atomicAdd(&g_sumsq[oslot * 1024 + tid], ssq[tid]);
    }
}

// ---------------------------------------------------------------------------
// Edge layers 3/5: gathered 128-dim edge feature @ W^T [64,128] -> hA + stats
// 128-row tile, 8x4 per thread, k-sliced 16
// ---------------------------------------------------------------------------
__global__ __launch_bounds__(256) void k_edgeG128(const float* __restrict__ W,
                                                  int srcSel, int oslot) {
    __shared__ __align__(16) float As[16][132];
    __shared__ __align__(16) float Bs[16][68];
    __shared__ int sP[128], sQ[128];
    __shared__ double ssum[64], ssq[64];
    const float* src = (srcSel == 1) ? g_x1 : g_x2;
    int e0 = blockIdx.x << 7, tid = threadIdx.x;
    if (tid < 64) { ssum[tid] = 0.0; ssq[tid] = 0.0; }
    if (tid < 128) {
        int e = e0 + tid;
        int p = e / KNN;
        sP[tid] = p;
        sQ[tid] = (p >> 12) * NN + g_idx[e];
    }
    int tx = tid & 15, ty = tid >> 4;
    int r8 = ty << 3, c4 = tx << 2;
    float acc[8][4] = {};
    for (int k0 = 0; k0 < 128; k0 += 16) {
        __syncthreads();
#pragma unroll
        for (int l = tid; l < 512; l += 256) {
            int r = l >> 2, kq = (l & 3) << 2;
            int c = k0 + kq;
            float4 av;
            if (c < 64) {
                float4 aq = *(const float4*)&src[(size_t)sQ[r] * 64 + c];
                float4 ap = *(const float4*)&src[(size_t)sP[r] * 64 + c];
                av.x = aq.x - ap.x; av.y = aq.y - ap.y;
                av.z = aq.z - ap.z; av.w = aq.w - ap.w;
            } else {
                av = *(const float4*)&src[(size_t)sP[r] * 64 + (c - 64)];
            }
            As[kq + 0][r] = av.x; As[kq + 1][r] = av.y;
            As[kq + 2][r] = av.z; As[kq + 3][r] = av.w;
        }
        {
            int r = tid >> 2, kq = (tid & 3) << 2;
            float4 bv = *(const float4*)&W[(size_t)r * 128 + k0 + kq];
            Bs[kq + 0][r] = bv.x; Bs[kq + 1][r] = bv.y;
            Bs[kq + 2][r] = bv.z; Bs[kq + 3][r] = bv.w;
        }
        __syncthreads();
#pragma unroll
        for (int k = 0; k < 16; k++) {
            float a[8], bb[4];
            *(float4*)&a[0]  = *(const float4*)&As[k][r8];
            *(float4*)&a[4]  = *(const float4*)&As[k][r8 + 4];
            *(float4*)&bb[0] = *(const float4*)&Bs[k][c4];
#pragma unroll
            for (int ii = 0; ii < 8; ii++)
#pragma unroll
                for (int jj = 0; jj < 4; jj++)
                    acc[ii][jj] = fmaf(a[ii], bb[jj], acc[ii][jj]);
        }
    }
#pragma unroll
    for (int ii = 0; ii < 8; ii++)
        *(float4*)&g_hA[(size_t)(e0 + r8 + ii) * 64 + c4] = *(float4*)&acc[ii][0];
#pragma unroll
    for (int jj = 0; jj < 4; jj++) {
        float s = 0.f, q = 0.f;
#pragma unroll
        for (int ii = 0; ii < 8; ii++) { float v = acc[ii][jj]; s += v; q = fmaf(v, v, q); }
        atomicAdd(&ssum[c4 + jj], (double)s);
        atomicAdd(&ssq[c4 + jj], (double)q);
    }
    __syncthreads();
    if (tid < 64) {
        atomicAdd(&g_sum[oslot * 1024 + tid], ssum[tid]);
        atomicAdd(&g_sumsq[oslot * 1024 + tid], ssq[tid]);
    }
}

// ---------------------------------------------------------------------------
// Point GEMMs, 128x128 tile, 8x8/thread, k-sliced 16. Modes:
//   0: A=[x1,x2,x3](192) @ W6                  -> h6 (stats slot 5)
//   1: A=[x1,x2,x3](192) @ W7[:,1024:] + gcorr -> h7 (stats slot 6)
//   2: A=act6(h7)(512)   @ W8                  -> h8 (stats slot 7)
// ---------------------------------------------------------------------------
__global__ __launch_bounds__(256) void k_point128(const float* __restrict__ W,
                                                  int Cin, int Cout, int wstride,
                                                  int woff, int mode, int aslot,
                                                  int outSel) {
    __shared__ __align__(16) float As[16][132];
    __shared__ __align__(16) float Bs[16][132];
    __shared__ double ssum[128], ssq[128];
    int c0 = blockIdx.x << 7, r0 = blockIdx.y << 7;
    int tid = threadIdx.x, tx = tid & 15, ty = tid >> 4;
    int r8 = ty << 3, c8 = tx << 3;
    int b = r0 >> 12;
    if (tid < 128) { ssum[tid] = 0.0; ssq[tid] = 0.0; }
    float acc[8][8] = {};
    for (int k0 = 0; k0 < Cin; k0 += 16) {
        __syncthreads();
#pragma unroll
        for (int l = tid; l < 512; l += 256) {
            int r = l >> 2, kq = (l & 3) << 2;
            int c = k0 + kq, row = r0 + r;
            float4 av;
            if (mode != 2) {
                const float* sp = (c < 64) ? &g_x1[(size_t)row * 64 + c]
                               : (c < 128) ? &g_x2[(size_t)row * 64 + (c - 64)]
                                           : &g_x3[(size_t)row * 64 + (c - 128)];
                av = *(const float4*)sp;
            } else {
                av = *(const float4*)&g_h7[(size_t)row * 512 + c];
                av.x = lrelu(av.x * g_scale[aslot * 1024 + c + 0] + g_bias[aslot * 1024 + c + 0]);
                av.y = lrelu(av.y * g_scale[aslot * 1024 + c + 1] + g_bias[aslot * 1024 + c + 1]);
                av.z = lrelu(av.z * g_scale[aslot * 1024 + c + 2] + g_bias[aslot * 1024 + c + 2]);
                av.w = lrelu(av.w * g_scale[aslot * 1024 + c + 3] + g_bias[aslot * 1024 + c + 3]);
            }
            As[kq + 0][r] = av.x; As[kq + 1][r] = av.y;
            As[kq + 2][r] = av.z; As[kq + 3][r] = av.w;
            float4 bv = *(const float4*)&W[(size_t)(c0 + r) * wstride + woff + k0 + kq];
            Bs[kq + 0][r] = bv.x; Bs[kq + 1][r] = bv.y;
            Bs[kq + 2][r] = bv.z; Bs[kq + 3][r] = bv.w;
        }
        __syncthreads();
#pragma unroll
        for (int k = 0; k < 16; k++) {
            float a[8], bb[8];
            *(float4*)&a[0]  = *(const float4*)&As[k][r8];
            *(float4*)&a[4]  = *(const float4*)&As[k][r8 + 4];
            *(float4*)&bb[0] = *(const float4*)&Bs[k][c8];
            *(float4*)&bb[4] = *(const float4*)&Bs[k][c8 + 4];
#pragma unroll
            for (int ii = 0; ii < 8; ii++)
#pragma unroll
                for (int jj = 0; jj < 8; jj++)
                    acc[ii][jj] = fmaf(a[ii], bb[jj], acc[ii][jj]);
        }
    }
    if (mode == 1) {
#pragma unroll
        for (int jj = 0; jj < 8; jj++) {
            float gc = g_gcorr[b * 512 + c0 + c8 + jj];
#pragma unroll
            for (int ii = 0; ii < 8; ii++) acc[ii][jj] += gc;
        }
    }
    float* out = (outSel == 0) ? g_h6 : (outSel == 1 ? g_h7 : g_h8);
#pragma unroll
    for (int ii = 0; ii < 8; ii++) {
        float* dst = &out[(size_t)(r0 + r8 + ii) * Cout + c0 + c8];
        *(float4*)&dst[0] = *(float4*)&acc[ii][0];
        *(float4*)&dst[4] = *(float4*)&acc[ii][4];
    }
    int slot = 5 + outSel;
#pragma unroll
    for (int jj = 0; jj < 8; jj++) {
        float s = 0.f, q = 0.f;
#pragma unroll
        for (int ii = 0; ii < 8; ii++) { float v = acc[ii][jj]; s += v; q = fmaf(v, v, q); }
        atomicAdd(&ssum[c8 + jj], (double)s);
        atomicAdd(&ssq[c8 + jj], (double)q);
    }
    __syncthreads();
    if (tid < 128) {
        atomicAdd(&g_sum[slot * 1024 + c0 + tid], ssum[tid]);
        atomicAdd(&g_sumsq[slot * 1024 + c0 + tid], ssq[tid]);
    }
}

// gcorr[b,o] = sum_c gmax[b,c] * W7[o,c]  (c < 1024); warp per output
__global__ void k_gcorr(const float* __restrict__ W7) {
    int b = blockIdx.y;
    int o = blockIdx.x * 8 + (threadIdx.x >> 5);
    int lane = threadIdx.x & 31;
    const float* gm = g_gmax + b * 1024;
    const float* w  = W7 + (size_t)o * 1216;
    float s = 0.f;
#pragma unroll 8
    for (int k = lane; k < 1024; k += 32) s = fmaf(gm[k], w[k], s);
#pragma unroll
    for (int off = 16; off; off >>= 1) s += __shfl_down_sync(0xffffffffu, s, off);
    if (lane == 0) g_gcorr[b * 512 + o] = s;
}

// fold (gamma, beta, mean, var) -> per-channel scale/bias (double path)
__global__ void k_fin(int slot, int C, double invM,
                      const float* __restrict__ g, const float* __restrict__ b) {
    int c = blockIdx.x * 256 + threadIdx.x;
    if (c >= C) return;
    double mean = g_sum[slot * 1024 + c] * invM;
    double var  = g_sumsq[slot * 1024 + c] * invM - mean * mean;
    float sc    = g[c] * rsqrtf((float)var + EPSBN);
    g_scale[slot * 1024 + c] = sc;
    g_bias[slot * 1024 + c]  = b[c] - (float)mean * sc;
}

// ---------------------------------------------------------------------------
// Max over k edges of act_slot(h) -> x{1,2,3}[P,64]
// ---------------------------------------------------------------------------
__global__ void k_maxe(int inSel, int slot, int outSel) {
    const float* h = (inSel == 0) ? g_hA : g_hB;
    float* out = (outSel == 1) ? g_x1 : (outSel == 2 ? g_x2 : g_x3);
    int t = blockIdx.x * 256 + threadIdx.x;
    if (t >= PT * 64) return;
    int p = t >> 6, c = t & 63;
    float sc = g_scale[slot * 1024 + c], bi = g_bias[slot * 1024 + c];
    const float* base = h + ((size_t)p * KNN) * 64 + c;
    float m = -3.0e38f;
#pragma unroll
    for (int j = 0; j < KNN; j++) {
        float v = lrelu(base[j * 64] * sc + bi);
        m = fmaxf(m, v);
    }
    out[t] = m;
}

// ---------------------------------------------------------------------------
// Global max pool over N of act5(h6): partial (16 chunks) + combine
// ---------------------------------------------------------------------------
__global__ __launch_bounds__(256) void k_gmax1() {
    int b = blockIdx.y, chunk = blockIdx.x, tid = threadIdx.x;
    float m[4]  = {-3.0e38f, -3.0e38f, -3.0e38f, -3.0e38f};
    float s[4], bi[4];
#pragma unroll
    for (int u = 0; u < 4; u++) {
        int c = tid + 256 * u;
        s[u]  = g_scale[5 * 1024 + c];
        bi[u] = g_bias[5 * 1024 + c];
    }
    for (int r = 0; r < 256; r++) {
        const float* hr = g_h6 + (size_t)(b * NN + chunk * 256 + r) * 1024;
#pragma unroll
        for (int u = 0; u < 4; u++) {
            float t = lrelu(hr[tid + 256 * u] * s[u] + bi[u]);
            m[u] = fmaxf(m[u], t);
        }
    }
#pragma unroll
    for (int u = 0; u < 4; u++)
        g_gpart[(size_t)(b * 16 + chunk) * 1024 + tid + 256 * u] = m[u];
}

__global__ void k_gmax2() {
    int t = blockIdx.x * 256 + threadIdx.x;
    if (t >= BB * 1024) return;
    int b = t >> 10, c = t & 1023;
    float m = -3.0e38f;
#pragma unroll
    for (int ch = 0; ch < 16; ch++)
        m = fmaxf(m, g_gpart[(size_t)(b * 16 + ch) * 1024 + c]);
    g_gmax[t] = m;
}

// ---------------------------------------------------------------------------
// Final: out[P,9] = act7(h8) @ W9^T
// ---------------------------------------------------------------------------
__global__ void k_out9(const float* __restrict__ W9, float* __restrict__ out) {
    int t = blockIdx.x * 256 + threadIdx.x;
    if (t >= PT * 9) return;
    int p = t / 9, o = t - p * 9;
    const float* row = g_h8 + (size_t)p * 256;
    const float* w   = W9 + o * 256;
    float acc = 0.f;
#pragma unroll 4
    for (int k = 0; k < 256; k++) {
        float v = lrelu(row[k] * g_scale[7 * 1024 + k] + g_bias[7 * 1024 + k]);
        acc = fmaf(v, w[k], acc);
    }
    out[t] = acc;
}

// ---------------------------------------------------------------------------
// Host launcher
// ---------------------------------------------------------------------------
extern "C" void kernel_launch(void* const* d_in, const int* in_sizes, int n_in,
                              void* d_out, int out_size) {
    int base = (in_sizes[1] == 1) ? 2 : 1;
    const float* x = (const float*)d_in[0];
    const float* W[9];
    const float* G[8];
    const float* Bt[8];
    for (int i = 0; i < 9; i++) W[i] = (const float*)d_in[base + i];
    for (int i = 0; i < 8; i++) {
        G[i]  = (const float*)d_in[base + 9 + 2 * i];
        Bt[i] = (const float*)d_in[base + 10 + 2 * i];
    }
    float* out = (float*)d_out;

    const double invE = 1.0 / (double)ET;
    const double invP = 1.0 / (double)PT;

    k_zero<<<32, 256>>>();
    k_prep3<<<PT / 256, 256>>>(x);

    // ---- stage 1: fused knn on xyz, edge layers 1-2, maxpool -> x1 ----
    k_topk3<<<PT, 128>>>();
    k_edge1<<<ET / 64, 256>>>(W[0]);
    k_fin<<<1, 256>>>(0, 64, invE, G[0], Bt[0]);
    k_edge128<<<ET / 128, 256>>>(W[1], 0, 1);
    k_fin<<<1, 256>>>(1, 64, invE, G[1], Bt[1]);
    k_maxe<<<PT * 64 / 256, 256>>>(1, 1, 1);

    // ---- stage 2: knn on x1, edge layers 3-4, maxpool -> x2 ----
    k_xx64<<<PT * 32 / 256, 256>>>(1);
    k_dist128sym<<<dim3(528, BB), 256>>>(1);
    k_topk<<<PT, 128>>>();
    k_edgeG128<<<ET / 128, 256>>>(W[2], 1, 2);
    k_fin<<<1, 256>>>(2, 64, invE, G[2], Bt[2]);
    k_edge128<<<ET / 128, 256>>>(W[3], 2, 3);
    k_fin<<<1, 256>>>(3, 64, invE, G[3], Bt[3]);
    k_maxe<<<PT * 64 / 256, 256>>>(1, 3, 2);

    // ---- stage 3: knn on x2, edge layer 5, maxpool -> x3 ----
    k_xx64<<<PT * 32 / 256, 256>>>(2);
    k_dist128sym<<<dim3(528, BB), 256>>>(2);
    k_topk<<<PT, 128>>>();
    k_edgeG128<<<ET / 128, 256>>>(W[4], 2, 4);
    k_fin<<<1, 256>>>(4, 64, invE, G[4], Bt[4]);
    k_maxe<<<PT * 64 / 256, 256>>>(0, 4, 3);

    // ---- point layers 6-9 ----
    k_point128<<<dim3(8, PT / 128), 256>>>(W[5], 192, 1024, 192, 0, 0, 0, 0);
    k_fin<<<4, 256>>>(5, 1024, invP, G[5], Bt[5]);
    k_gmax1<<<dim3(16, BB), 256>>>();
    k_gmax2<<<32, 256>>>();
    k_gcorr<<<dim3(64, BB), 256>>>(W[6]);
    k_point128<<<dim3(4, PT / 128), 256>>>(W[6], 192, 512, 1216, 1024, 1, 0, 1);
    k_fin<<<2, 256>>>(6, 512, invP, G[6], Bt[6]);
    k_point128<<<dim3(2, PT / 128), 256>>>(W[7], 512, 256, 512, 0, 2, 6, 2);
    k_fin<<<1, 256>>>(7, 256, invP, G[7], Bt[7]);
    k_out9<<<(PT * 9 + 255) / 256, 256>>>(W[8], out);
}